// round 5
// baseline (speedup 1.0000x reference)
#include <cuda_runtime.h>
#include <cuda_bf16.h>
#include <math.h>
#include <stdint.h>

#define NN   50000
#define EE   500000
#define GG   64
#define DIN  128
#define ED   32
#define H1   256
#define H2   128
#define HD   64
#define OUTD 8
#define NCHUNK 49   // ceil(NN/1024)

// ---------------- scratch (device globals; no allocation allowed) ----------
__device__ float g_xl[(size_t)NN * H1];
__device__ float g_xr[(size_t)NN * H1];
__device__ float g_h1[(size_t)NN * H1];
__device__ float g_h2[(size_t)NN * H2];
__device__ float g_escore[EE];
__device__ float g_eself[NN];
__device__ float g_loopattr[(size_t)NN * ED];
__device__ int   g_deg[NN];
__device__ int   g_ptr[NN + 1];
__device__ int   g_cur[NN];
__device__ int   g_eid[EE];
__device__ int   g_bsum[64];
__device__ float g_pool[GG * H2];
// bf16 hi/lo staging for tensor-core GEMMs
__device__ __nv_bfloat16 g_xhi[(size_t)NN * H1];
__device__ __nv_bfloat16 g_xlo[(size_t)NN * H1];
__device__ __nv_bfloat16 g_whi[2 * 256 * 256];
__device__ __nv_bfloat16 g_wlo[2 * 256 * 256];

// ======================= helpers ==========================================
__device__ __forceinline__ uint32_t smem_u32(const void* p) {
    uint32_t a;
    asm("{ .reg .u64 t; cvta.to.shared.u64 t, %1; cvt.u32.u64 %0, t; }" : "=r"(a) : "l"(p));
    return a;
}
// pack two f32 (k-order: lo_k first) into bf16x2 word (low half = lo_k)
__device__ __forceinline__ uint32_t packbf(float lo_k, float hi_k) {
    uint32_t r;
    asm("cvt.rn.bf16x2.f32 %0, %1, %2;" : "=r"(r) : "f"(hi_k), "f"(lo_k));
    return r;
}
__device__ __forceinline__ void ldm_x4(uint32_t (&r)[4], uint32_t addr) {
    asm volatile("ldmatrix.sync.aligned.m8n8.x4.shared.b16 {%0,%1,%2,%3}, [%4];"
        : "=r"(r[0]), "=r"(r[1]), "=r"(r[2]), "=r"(r[3]) : "r"(addr));
}
__device__ __forceinline__ void ldm_x2t(uint32_t (&r)[2], uint32_t addr) {
    asm volatile("ldmatrix.sync.aligned.m8n8.x2.trans.shared.b16 {%0,%1}, [%2];"
        : "=r"(r[0]), "=r"(r[1]) : "r"(addr));
}
__device__ __forceinline__ void mma_bf16(float (&c)[4], const uint32_t (&a)[4],
                                         const uint32_t (&b)[2]) {
    asm volatile("mma.sync.aligned.m16n8k16.row.col.f32.bf16.bf16.f32 "
        "{%0,%1,%2,%3},{%4,%5,%6,%7},{%8,%9},{%0,%1,%2,%3};"
        : "+f"(c[0]), "+f"(c[1]), "+f"(c[2]), "+f"(c[3])
        : "r"(a[0]), "r"(a[1]), "r"(a[2]), "r"(a[3]), "r"(b[0]), "r"(b[1]));
}
#define CP16(s, g)   asm volatile("cp.async.cg.shared.global [%0], [%1], 16;" :: "r"(s), "l"(g))
#define CP_COMMIT()  asm volatile("cp.async.commit_group;" ::: "memory")
#define CP_WAIT0()   asm volatile("cp.async.wait_group 0;" ::: "memory")
#define CP_WAIT1()   asm volatile("cp.async.wait_group 1;" ::: "memory")

// ---------------- f32x2 packed helpers ----------------
__device__ __forceinline__ unsigned long long ffma2(unsigned long long a,
                                                    unsigned long long b,
                                                    unsigned long long c) {
    unsigned long long d;
    asm("fma.rn.f32x2 %0, %1, %2, %3;" : "=l"(d) : "l"(a), "l"(b), "l"(c));
    return d;
}
__device__ __forceinline__ unsigned long long dupf(float x) {
    unsigned long long r;
    asm("mov.b64 %0, {%1, %1};" : "=l"(r) : "f"(x));
    return r;
}
__device__ __forceinline__ float2 unpk(unsigned long long v) {
    float2 r;
    asm("mov.b64 {%0, %1}, %2;" : "=f"(r.x), "=f"(r.y) : "l"(v));
    return r;
}

// ======================= setup kernels ====================================
__global__ void k_hist(const int* __restrict__ edst) {
    int e = blockIdx.x * blockDim.x + threadIdx.x;
    if (e < EE) atomicAdd(&g_deg[edst[e]], 1);
}

__global__ void k_scan_partial() {
    __shared__ int sh[32];
    int tid = threadIdx.x;
    int i = blockIdx.x * 1024 + tid;
    int v = (i < NN) ? g_deg[i] : 0;
#pragma unroll
    for (int o = 16; o; o >>= 1) v += __shfl_xor_sync(0xffffffffu, v, o);
    if ((tid & 31) == 0) sh[tid >> 5] = v;
    __syncthreads();
    if (tid < 32) {
        int t = sh[tid];
#pragma unroll
        for (int o = 16; o; o >>= 1) t += __shfl_xor_sync(0xffffffffu, t, o);
        if (tid == 0) g_bsum[blockIdx.x] = t;
    }
}

__global__ void k_scan_bsum() {
    __shared__ int sh[64];
    int tid = threadIdx.x;
    int v = (tid < NCHUNK) ? g_bsum[tid] : 0;
    sh[tid] = v;
    __syncthreads();
    for (int off = 1; off < 64; off <<= 1) {
        int t = (tid >= off) ? sh[tid - off] : 0;
        __syncthreads();
        sh[tid] += t;
        __syncthreads();
    }
    if (tid < NCHUNK) g_bsum[tid] = sh[tid] - v;   // exclusive
    if (tid == 0) g_ptr[NN] = EE;
}

__global__ void k_scan_final() {
    __shared__ int sh[32];
    int tid = threadIdx.x, lane = tid & 31, wid = tid >> 5;
    int i = blockIdx.x * 1024 + tid;
    int v = (i < NN) ? g_deg[i] : 0;
    int incl = v;
#pragma unroll
    for (int o = 1; o < 32; o <<= 1) {
        int t = __shfl_up_sync(0xffffffffu, incl, o);
        if (lane >= o) incl += t;
    }
    if (lane == 31) sh[wid] = incl;
    __syncthreads();
    if (wid == 0) {
        int t = sh[lane];
#pragma unroll
        for (int o = 1; o < 32; o <<= 1) {
            int u = __shfl_up_sync(0xffffffffu, t, o);
            if (lane >= o) t += u;
        }
        sh[lane] = t;
    }
    __syncthreads();
    int base = g_bsum[blockIdx.x] + (wid ? sh[wid - 1] : 0);
    if (i < NN) g_ptr[i] = base + incl - v;
}

__global__ void k_scatter(const int* __restrict__ edst) {
    int e = blockIdx.x * blockDim.x + threadIdx.x;
    if (e >= EE) return;
    int d = edst[e];
    int pos = atomicAdd(&g_cur[d], 1);
    g_eid[g_ptr[d] + pos] = e;
}

__global__ void k_loopmean(const float* __restrict__ eattr) {
    int gw = (blockIdx.x * blockDim.x + threadIdx.x) >> 5;
    int lane = threadIdx.x & 31;
    if (gw >= NN) return;
    int beg = g_ptr[gw], end = g_ptr[gw + 1];
    float acc = 0.f;
    for (int t = beg; t < end; t++)
        acc += eattr[(size_t)g_eid[t] * ED + lane];
    g_loopattr[(size_t)gw * ED + lane] = acc / fmaxf((float)(end - beg), 1.f);
}

// ======================= fp32 -> bf16 hi/lo conversion ====================
__global__ void k_convert(const float* __restrict__ src,
                          __nv_bfloat16* __restrict__ hi,
                          __nv_bfloat16* __restrict__ lo, int n4) {
    int i = blockIdx.x * blockDim.x + threadIdx.x;
    if (i >= n4) return;
    float4 v = ((const float4*)src)[i];
    uint32_t h01 = packbf(v.x, v.y);
    uint32_t h23 = packbf(v.z, v.w);
    float r0 = v.x - __uint_as_float(h01 << 16);
    float r1 = v.y - __uint_as_float(h01 & 0xffff0000u);
    float r2 = v.z - __uint_as_float(h23 << 16);
    float r3 = v.w - __uint_as_float(h23 & 0xffff0000u);
    uint2 hv = make_uint2(h01, h23);
    uint2 lv = make_uint2(packbf(r0, r1), packbf(r2, r3));
    ((uint2*)hi)[i] = hv;
    ((uint2*)lo)[i] = lv;
}

// ======================= bf16x3 GEMM, cp.async double-buffered ============
// C[M,Nc] = A[M,KTOT] @ W[KTOT,Nc] + bias, A/W pre-split into bf16 hi/lo.
// grid (ceil(M/128), Nc/64, 2); z selects weight set + bias + out.
// CTA 128x64, K-chunk 32, 8 warps 4(M)x2(N), warp tile 32x32.
// smem stage: Ahi 128x80B | Alo 128x80B | Bhi 32x144B | Blo 32x144B = 29696B
#define STG 29696
#define A_LO_OFF 10240
#define B_HI_OFF 20480
#define B_LO_OFF 25088

template <int KTOT>
__global__ void __launch_bounds__(256, 2)
k_mma3(const __nv_bfloat16* __restrict__ Ahi, const __nv_bfloat16* __restrict__ Alo,
       const float* __restrict__ bias0, float* __restrict__ out0,
       const float* __restrict__ bias1, float* __restrict__ out1,
       int M, int Nc) {
    extern __shared__ char smem[];
    uint32_t sb = smem_u32(smem);
    int tid = threadIdx.x, lane = tid & 31, w = tid >> 5;
    int wm = w & 3, wn = w >> 2;
    const float* bias = blockIdx.z ? bias1 : bias0;
    float* out        = blockIdx.z ? out1 : out0;
    const __nv_bfloat16* Whi = g_whi + (size_t)blockIdx.z * KTOT * Nc;
    const __nv_bfloat16* Wlo = g_wlo + (size_t)blockIdx.z * KTOT * Nc;
    int row0 = blockIdx.x * 128, c0 = blockIdx.y * 64;
    constexpr int NK = KTOT / 32;

    float acc[2][4][4];
#pragma unroll
    for (int i = 0; i < 2; i++)
#pragma unroll
        for (int j = 0; j < 4; j++)
#pragma unroll
            for (int q = 0; q < 4; q++) acc[i][j][q] = 0.f;

    auto load_stage = [&](int stage, int k0) {
        uint32_t base = sb + stage * STG;
        // A: 128 rows x 32 bf16 (64B = 4 x 16B); 512 segs hi + 512 lo
#pragma unroll
        for (int t = 0; t < 2; t++) {
            int seg = t * 256 + tid;
            int r = seg >> 2, c16 = seg & 3;
            if (row0 + r < M) {
                size_t go = (size_t)(row0 + r) * KTOT + k0 + c16 * 8;
                CP16(base + r * 80 + c16 * 16, Ahi + go);
                CP16(base + A_LO_OFF + r * 80 + c16 * 16, Alo + go);
            }
        }
        // B: 32 rows x 64 bf16 (128B = 8 x 16B); 256 segs hi + 256 lo
        {
            int r = tid >> 3, c16 = tid & 7;
            size_t go = (size_t)(k0 + r) * Nc + c0 + c16 * 8;
            CP16(base + B_HI_OFF + r * 144 + c16 * 16, Whi + go);
            CP16(base + B_LO_OFF + r * 144 + c16 * 16, Wlo + go);
        }
    };

    load_stage(0, 0);
    CP_COMMIT();

    for (int i = 0; i < NK; i++) {
        int cur = i & 1;
        if (i + 1 < NK) {
            load_stage(cur ^ 1, (i + 1) * 32);
            CP_COMMIT();
            CP_WAIT1();
        } else {
            CP_WAIT0();
        }
        __syncthreads();

        uint32_t aHiB = sb + cur * STG;
        uint32_t aLoB = aHiB + A_LO_OFF;
        uint32_t bHiB = aHiB + B_HI_OFF;
        uint32_t bLoB = aHiB + B_LO_OFF;
#pragma unroll
        for (int s = 0; s < 2; s++) {
            uint32_t aH[2][4], aL[2][4];
#pragma unroll
            for (int ii = 0; ii < 2; ii++) {
                int tile = lane >> 3, rr = lane & 7;
                int row = wm * 32 + ii * 16 + (tile & 1) * 8 + rr;
                int kk = s * 16 + (tile >> 1) * 8;
                uint32_t off = (uint32_t)(row * 80) + (uint32_t)kk * 2u;
                ldm_x4(aH[ii], aHiB + off);
                ldm_x4(aL[ii], aLoB + off);
            }
            uint32_t bH[4][2], bL[4][2];
#pragma unroll
            for (int j = 0; j < 4; j++) {
                int krow = s * 16 + (lane & 15);
                int ncol = wn * 32 + j * 8;
                uint32_t off = (uint32_t)(krow * 144) + (uint32_t)ncol * 2u;
                ldm_x2t(bH[j], bHiB + off);
                ldm_x2t(bL[j], bLoB + off);
            }
#pragma unroll
            for (int ii = 0; ii < 2; ii++)
#pragma unroll
                for (int j = 0; j < 4; j++) {
                    mma_bf16(acc[ii][j], aH[ii], bH[j]);
                    mma_bf16(acc[ii][j], aH[ii], bL[j]);
                    mma_bf16(acc[ii][j], aL[ii], bH[j]);
                }
        }
        __syncthreads();
    }

    // ---- epilogue
    int g = lane >> 2, tg = lane & 3;
#pragma unroll
    for (int i = 0; i < 2; i++) {
        int r1 = row0 + wm * 32 + i * 16 + g;
        int r2 = r1 + 8;
#pragma unroll
        for (int j = 0; j < 4; j++) {
            int col = c0 + wn * 32 + j * 8 + tg * 2;
            float2 bv = *(const float2*)&bias[col];
            if (r1 < M) {
                float2 o = make_float2(acc[i][j][0] + bv.x, acc[i][j][1] + bv.y);
                *(float2*)&out[(size_t)r1 * Nc + col] = o;
            }
            if (r2 < M) {
                float2 o = make_float2(acc[i][j][2] + bv.x, acc[i][j][3] + bv.y);
                *(float2*)&out[(size_t)r2 * Nc + col] = o;
            }
        }
    }
}

// ======================= fused edge-score GEMM (no atomics) ===============
// 64 edges x ALL C cols per block. Lane owns cols {lane, lane+32, ...} so all
// smem/gmem accesses are conflict-free / coalesced. f32x2 packs edge pairs.
template <int C>
__global__ void __launch_bounds__(256)
k_score2(const float* __restrict__ eattr, const float* __restrict__ We,
         const int* __restrict__ esrc, const int* __restrict__ edst,
         const float* __restrict__ att,
         const float* __restrict__ xl, const float* __restrict__ xr) {
    constexpr int CPL = C / 32;               // cols per lane
    __shared__ uint32_t AsU[ED][64];          // [k][edge] fp32 bits, 8KB
    __shared__ float Bs[ED][C];               // We [k][col]
    __shared__ int ssrc[64], sdst[64];
    int tid = threadIdx.x, w = tid >> 5, lane = tid & 31;
    int r0 = blockIdx.x * 64;

    for (int idx = tid; idx < 64 * 8; idx += 256) {
        int e = idx >> 3, c4 = (idx & 7) * 4;
        float4 v = make_float4(0.f, 0.f, 0.f, 0.f);
        if (r0 + e < EE) v = *(const float4*)&eattr[(size_t)(r0 + e) * ED + c4];
        AsU[c4 + 0][e] = __float_as_uint(v.x);
        AsU[c4 + 1][e] = __float_as_uint(v.y);
        AsU[c4 + 2][e] = __float_as_uint(v.z);
        AsU[c4 + 3][e] = __float_as_uint(v.w);
    }
    for (int idx = tid; idx < ED * (C / 4); idx += 256) {
        int k = idx / (C / 4), c = (idx % (C / 4)) * 4;
        *(float4*)&Bs[k][c] = *(const float4*)&We[(size_t)k * C + c];
    }
    if (tid < 64) {
        int e = r0 + tid;
        ssrc[tid] = (e < EE) ? esrc[e] : 0;
        sdst[tid] = (e < EE) ? edst[e] : 0;
    }
    __syncthreads();

    unsigned long long acc2[4][CPL];
#pragma unroll
    for (int p = 0; p < 4; p++)
#pragma unroll
        for (int j = 0; j < CPL; j++) acc2[p][j] = 0ull;

#pragma unroll
    for (int k = 0; k < ED; k++) {
        ulonglong2 aA = *(const ulonglong2*)&AsU[k][w * 8];
        ulonglong2 aB = *(const ulonglong2*)&AsU[k][w * 8 + 4];
        unsigned long long a[4] = {aA.x, aA.y, aB.x, aB.y};
#pragma unroll
        for (int j = 0; j < CPL; j++) {
            unsigned long long b = dupf(Bs[k][lane + 32 * j]);  // conflict-free
#pragma unroll
            for (int p = 0; p < 4; p++)
                acc2[p][j] = ffma2(a[p], b, acc2[p][j]);
        }
    }

    float attv[CPL];
#pragma unroll
    for (int j = 0; j < CPL; j++) attv[j] = att[lane + 32 * j];

#pragma unroll
    for (int p = 0; p < 4; p++) {
        int e0i = w * 8 + 2 * p, e1i = e0i + 1;
        const float* xl0 = &xl[(size_t)ssrc[e0i] * C + lane];
        const float* xr0 = &xr[(size_t)sdst[e0i] * C + lane];
        const float* xl1 = &xl[(size_t)ssrc[e1i] * C + lane];
        const float* xr1 = &xr[(size_t)sdst[e1i] * C + lane];
        float pe0 = 0.f, pe1 = 0.f;
#pragma unroll
        for (int j = 0; j < CPL; j++) {
            float2 v = unpk(acc2[p][j]);
            float t0 = v.x + xl0[32 * j] + xr0[32 * j]; t0 = t0 > 0.f ? t0 : 0.2f * t0;
            float t1 = v.y + xl1[32 * j] + xr1[32 * j]; t1 = t1 > 0.f ? t1 : 0.2f * t1;
            pe0 += attv[j] * t0;
            pe1 += attv[j] * t1;
        }
#pragma unroll
        for (int o = 16; o; o >>= 1) {
            pe0 += __shfl_xor_sync(0xffffffffu, pe0, o);
            pe1 += __shfl_xor_sync(0xffffffffu, pe1, o);
        }
        if (lane == 0) {
            if (r0 + e0i < EE) g_escore[r0 + e0i] = pe0;
            if (r0 + e1i < EE) g_escore[r0 + e1i] = pe1;
        }
    }
}

// ======================= self-loop score per node =========================
template <int C>
__global__ void k_eself(const float* __restrict__ We, const float* __restrict__ att,
                        const float* __restrict__ xl, const float* __restrict__ xr) {
    int gw = (blockIdx.x * blockDim.x + threadIdx.x) >> 5;
    int lane = threadIdx.x & 31;
    if (gw >= NN) return;
    float la = g_loopattr[(size_t)gw * ED + lane];
    float acc = 0.f;
#pragma unroll
    for (int jj = 0; jj < C / 32; jj++) {
        int j = jj * 32 + lane;
        float v = xl[(size_t)gw * C + j] + xr[(size_t)gw * C + j];
#pragma unroll
        for (int k = 0; k < ED; k++)
            v += __shfl_sync(0xffffffffu, la, k) * We[k * C + j];
        v = v > 0.f ? v : 0.2f * v;
        acc += att[j] * v;
    }
#pragma unroll
    for (int off = 16; off; off >>= 1) acc += __shfl_xor_sync(0xffffffffu, acc, off);
    if (lane == 0) g_eself[gw] = acc;
}

// ======================= softmax + aggregation (warp/node) ================
template <int C>
__global__ void k_aggregate(const int* __restrict__ esrc,
                            const float* __restrict__ xl,
                            const float* __restrict__ bias,
                            float* __restrict__ outp) {
    int gw = (blockIdx.x * blockDim.x + threadIdx.x) >> 5;
    int lane = threadIdx.x & 31;
    if (gw >= NN) return;
    int beg = g_ptr[gw], end = g_ptr[gw + 1];

    float m = g_eself[gw];
    for (int t = beg + lane; t < end; t += 32) m = fmaxf(m, g_escore[g_eid[t]]);
#pragma unroll
    for (int off = 16; off; off >>= 1) m = fmaxf(m, __shfl_xor_sync(0xffffffffu, m, off));

    float4 acc[C / 128];
#pragma unroll
    for (int jj = 0; jj < C / 128; jj++) acc[jj] = make_float4(0.f, 0.f, 0.f, 0.f);
    float denom = 0.f;

    for (int t = beg; t < end; t++) {
        int eid = g_eid[t];
        float w = expf(g_escore[eid] - m);
        int s = esrc[eid];
        denom += w;
#pragma unroll
        for (int jj = 0; jj < C / 128; jj++) {
            float4 x4 = *(const float4*)&xl[(size_t)s * C + jj * 128 + lane * 4];
            acc[jj].x += w * x4.x; acc[jj].y += w * x4.y;
            acc[jj].z += w * x4.z; acc[jj].w += w * x4.w;
        }
    }
    float ws = expf(g_eself[gw] - m);
    denom += ws;
#pragma unroll
    for (int jj = 0; jj < C / 128; jj++) {
        float4 x4 = *(const float4*)&xl[(size_t)gw * C + jj * 128 + lane * 4];
        acc[jj].x += ws * x4.x; acc[jj].y += ws * x4.y;
        acc[jj].z += ws * x4.z; acc[jj].w += ws * x4.w;
    }

    float inv = 1.f / denom;
#pragma unroll
    for (int jj = 0; jj < C / 128; jj++) {
        int c = jj * 128 + lane * 4;
        float4 b4 = *(const float4*)&bias[c];
        float4 o;
        o.x = fmaxf(acc[jj].x * inv + b4.x, 0.f);
        o.y = fmaxf(acc[jj].y * inv + b4.y, 0.f);
        o.z = fmaxf(acc[jj].z * inv + b4.z, 0.f);
        o.w = fmaxf(acc[jj].w * inv + b4.w, 0.f);
        *(float4*)&outp[(size_t)gw * C + c] = o;
    }
}

// ======================= global mean pool =================================
#define NPB 196
__global__ void k_pool2(const int* __restrict__ batch) {
    int tid = threadIdx.x;                 // 128 threads = H2 columns
    int n0 = blockIdx.x * NPB;
    int n1 = min(n0 + NPB, NN);
    if (n0 >= n1) return;
    int curg = batch[n0];
    float acc = 0.f;
    for (int n = n0; n < n1; n++) {
        int g = batch[n];
        if (g != curg) {
            atomicAdd(&g_pool[curg * H2 + tid], acc);
            acc = 0.f;
            curg = g;
        }
        acc += g_h2[(size_t)n * H2 + tid];
    }
    atomicAdd(&g_pool[curg * H2 + tid], acc);
}

// ======================= MLP head =========================================
__device__ __forceinline__ int lowerb(const int* b, int val) {
    int lo = 0, hi = NN;
    while (lo < hi) { int m = (lo + hi) >> 1; if (b[m] < val) lo = m + 1; else hi = m; }
    return lo;
}

__global__ void k_head(const int* __restrict__ batch,
                       const float* __restrict__ Wd1, const float* __restrict__ bd1,
                       const float* __restrict__ gma, const float* __restrict__ bta,
                       const float* __restrict__ mean, const float* __restrict__ var,
                       const float* __restrict__ Wd2, const float* __restrict__ bd2,
                       float* __restrict__ out) {
    __shared__ float sp[GG * H2];
    __shared__ float sh[GG * HD];
    __shared__ float scnt[GG];
    int tid = threadIdx.x;
    if (tid < GG)
        scnt[tid] = (float)(lowerb(batch, tid + 1) - lowerb(batch, tid));
    __syncthreads();
    for (int idx = tid; idx < GG * H2; idx += blockDim.x) {
        int g = idx / H2;
        sp[idx] = g_pool[idx] / fmaxf(scnt[g], 1.f);
    }
    __syncthreads();
    for (int idx = tid; idx < GG * HD; idx += blockDim.x) {
        int g = idx / HD, h = idx - g * HD;
        float a = bd1[h];
        for (int k = 0; k < H2; k++) a += sp[g * H2 + k] * Wd1[k * HD + h];
        a = (a - mean[h]) / sqrtf(var[h] + 1e-5f) * gma[h] + bta[h];
        a = a > 0.f ? a : 0.1f * a;
        sh[idx] = a;
    }
    __syncthreads();
    for (int idx = tid; idx < GG * OUTD; idx += blockDim.x) {
        int g = idx / OUTD, o = idx - g * OUTD;
        float a = bd2[o];
        for (int k = 0; k < HD; k++) a += sh[g * HD + k] * Wd2[k * OUTD + o];
        out[idx] = a;
    }
}

// ======================= launcher =========================================
extern "C" void kernel_launch(void* const* d_in, const int* in_sizes, int n_in,
                              void* d_out, int out_size) {
    const float* node_attr = (const float*)d_in[0];
    const float* edge_attr = (const float*)d_in[1];
    const int*   esrc      = (const int*)d_in[2];
    const int*   edst      = (const int*)d_in[3];
    const int*   batch     = (const int*)d_in[4];
    const float *Wl1 = (const float*)d_in[5],  *bl1 = (const float*)d_in[6];
    const float *Wr1 = (const float*)d_in[7],  *br1 = (const float*)d_in[8];
    const float *We1 = (const float*)d_in[9],  *att1 = (const float*)d_in[10], *b1 = (const float*)d_in[11];
    const float *Wl2 = (const float*)d_in[12], *bl2 = (const float*)d_in[13];
    const float *Wr2 = (const float*)d_in[14], *br2 = (const float*)d_in[15];
    const float *We2 = (const float*)d_in[16], *att2 = (const float*)d_in[17], *b2 = (const float*)d_in[18];
    const float *Wd1 = (const float*)d_in[19], *bd1 = (const float*)d_in[20];
    const float *gma = (const float*)d_in[21], *bta = (const float*)d_in[22];
    const float *mean = (const float*)d_in[23], *var = (const float*)d_in[24];
    const float *Wd2 = (const float*)d_in[25], *bd2 = (const float*)d_in[26];
    float* out = (float*)d_out;

    float *p_xl, *p_xr, *p_h1, *p_h2, *p_pool;
    int *p_deg, *p_cur;
    __nv_bfloat16 *p_xhi, *p_xlo, *p_whi, *p_wlo;
    cudaGetSymbolAddress((void**)&p_xl, g_xl);
    cudaGetSymbolAddress((void**)&p_xr, g_xr);
    cudaGetSymbolAddress((void**)&p_h1, g_h1);
    cudaGetSymbolAddress((void**)&p_h2, g_h2);
    cudaGetSymbolAddress((void**)&p_pool, g_pool);
    cudaGetSymbolAddress((void**)&p_deg, g_deg);
    cudaGetSymbolAddress((void**)&p_cur, g_cur);
    cudaGetSymbolAddress((void**)&p_xhi, g_xhi);
    cudaGetSymbolAddress((void**)&p_xlo, g_xlo);
    cudaGetSymbolAddress((void**)&p_whi, g_whi);
    cudaGetSymbolAddress((void**)&p_wlo, g_wlo);

    const int MMA_SMEM = 2 * STG;
    cudaFuncSetAttribute(k_mma3<128>, cudaFuncAttributeMaxDynamicSharedMemorySize, MMA_SMEM);
    cudaFuncSetAttribute(k_mma3<256>, cudaFuncAttributeMaxDynamicSharedMemorySize, MMA_SMEM);

    cudaMemsetAsync(p_deg, 0, NN * sizeof(int), 0);
    cudaMemsetAsync(p_cur, 0, NN * sizeof(int), 0);
    cudaMemsetAsync(p_pool, 0, GG * H2 * sizeof(float), 0);

    int nodeWB = (NN * 32 + 255) / 256;   // warp-per-node blocks
    int rowT = (NN + 127) / 128;          // 391

    // setup + layer-1 conversions/GEMM interleaved
    k_hist<<<(EE + 255) / 256, 256>>>(edst);
    k_scan_partial<<<NCHUNK, 1024>>>();
    k_scan_bsum<<<1, 64>>>();
    // convert inputs + weights for layer 1
    k_convert<<<(NN * DIN / 4 + 255) / 256, 256>>>(node_attr, p_xhi, p_xlo, NN * DIN / 4);
    k_convert<<<(DIN * H1 / 4 + 255) / 256, 256>>>(Wl1, p_whi, p_wlo, DIN * H1 / 4);
    k_convert<<<(DIN * H1 / 4 + 255) / 256, 256>>>(Wr1, p_whi + DIN * H1, p_wlo + DIN * H1, DIN * H1 / 4);
    k_mma3<DIN><<<dim3(rowT, H1 / 64, 2), 256, MMA_SMEM>>>(
        p_xhi, p_xlo, bl1, p_xl, br1, p_xr, NN, H1);
    k_scan_final<<<NCHUNK, 1024>>>();
    k_scatter<<<(EE + 255) / 256, 256>>>(edst);
    k_loopmean<<<nodeWB, 256>>>(edge_attr);

    // ---------------- layer 1 ----------------
    k_score2<H1><<<(EE + 63) / 64, 256>>>(edge_attr, We1, esrc, edst, att1, p_xl, p_xr);
    k_eself<H1><<<nodeWB, 256>>>(We1, att1, p_xl, p_xr);
    k_aggregate<H1><<<nodeWB, 256>>>(esrc, p_xl, b1, p_h1);

    // ---------------- layer 2 ----------------
    k_convert<<<(NN * H1 / 4 + 255) / 256, 256>>>(p_h1, p_xhi, p_xlo, NN * H1 / 4);
    k_convert<<<(H1 * H2 / 4 + 255) / 256, 256>>>(Wl2, p_whi, p_wlo, H1 * H2 / 4);
    k_convert<<<(H1 * H2 / 4 + 255) / 256, 256>>>(Wr2, p_whi + H1 * H2, p_wlo + H1 * H2, H1 * H2 / 4);
    k_mma3<H1><<<dim3(rowT, H2 / 64, 2), 256, MMA_SMEM>>>(
        p_xhi, p_xlo, bl2, p_xl, br2, p_xr, NN, H2);
    k_score2<H2><<<(EE + 63) / 64, 256>>>(edge_attr, We2, esrc, edst, att2, p_xl, p_xr);
    k_eself<H2><<<nodeWB, 256>>>(We2, att2, p_xl, p_xr);
    k_aggregate<H2><<<nodeWB, 256>>>(esrc, p_xl, b2, p_h2);

    // ---------------- pool + head ----------------
    k_pool2<<<(NN + NPB - 1) / NPB, 128>>>(batch);
    k_head<<<1, 512>>>(batch, Wd1, bd1, gma, bta, mean, var, Wd2, bd2, out);
}

// round 6
// speedup vs baseline: 1.0493x; 1.0493x over previous
#include <cuda_runtime.h>
#include <cuda_bf16.h>
#include <math.h>
#include <stdint.h>

#define NN   50000
#define EE   500000
#define GG   64
#define DIN  128
#define ED   32
#define H1   256
#define H2   128
#define HD   64
#define OUTD 8
#define NCHUNK 49   // ceil(NN/1024)

// ---------------- scratch (device globals; no allocation allowed) ----------
__device__ float g_xl[(size_t)NN * H1];
__device__ float g_xr[(size_t)NN * H1];
__device__ float g_h1[(size_t)NN * H1];
__device__ float g_h2[(size_t)NN * H2];
__device__ float g_escore[EE];
__device__ float g_eself[NN];
__device__ float g_loopattr[(size_t)NN * ED];
__device__ int   g_deg[NN];
__device__ int   g_ptr[NN + 1];
__device__ int   g_cur[NN];
__device__ int   g_eid[EE];
__device__ int   g_bsum[64];
__device__ float g_pool[GG * H2];

// ======================= helpers ==========================================
__device__ __forceinline__ uint32_t smem_u32(const void* p) {
    uint32_t a;
    asm("{ .reg .u64 t; cvta.to.shared.u64 t, %1; cvt.u32.u64 %0, t; }" : "=r"(a) : "l"(p));
    return a;
}
// pack two f32 (k-order: lo_k first) into bf16x2 word (low half = lo_k)
__device__ __forceinline__ uint32_t packbf(float lo_k, float hi_k) {
    uint32_t r;
    asm("cvt.rn.bf16x2.f32 %0, %1, %2;" : "=r"(r) : "f"(hi_k), "f"(lo_k));
    return r;
}
__device__ __forceinline__ void ldm_x4(uint32_t (&r)[4], uint32_t addr) {
    asm volatile("ldmatrix.sync.aligned.m8n8.x4.shared.b16 {%0,%1,%2,%3}, [%4];"
        : "=r"(r[0]), "=r"(r[1]), "=r"(r[2]), "=r"(r[3]) : "r"(addr));
}
__device__ __forceinline__ void ldm_x4t(uint32_t (&r)[4], uint32_t addr) {
    asm volatile("ldmatrix.sync.aligned.m8n8.x4.trans.shared.b16 {%0,%1,%2,%3}, [%4];"
        : "=r"(r[0]), "=r"(r[1]), "=r"(r[2]), "=r"(r[3]) : "r"(addr));
}
__device__ __forceinline__ void mma_bf16(float (&c)[4], const uint32_t (&a)[4],
                                         uint32_t b0, uint32_t b1) {
    asm volatile("mma.sync.aligned.m16n8k16.row.col.f32.bf16.bf16.f32 "
        "{%0,%1,%2,%3},{%4,%5,%6,%7},{%8,%9},{%0,%1,%2,%3};"
        : "+f"(c[0]), "+f"(c[1]), "+f"(c[2]), "+f"(c[3])
        : "r"(a[0]), "r"(a[1]), "r"(a[2]), "r"(a[3]), "r"(b0), "r"(b1));
}

// ---------------- f32x2 packed helpers ----------------
__device__ __forceinline__ unsigned long long ffma2(unsigned long long a,
                                                    unsigned long long b,
                                                    unsigned long long c) {
    unsigned long long d;
    asm("fma.rn.f32x2 %0, %1, %2, %3;" : "=l"(d) : "l"(a), "l"(b), "l"(c));
    return d;
}
__device__ __forceinline__ unsigned long long dupf(float x) {
    unsigned long long r;
    asm("mov.b64 %0, {%1, %1};" : "=l"(r) : "f"(x));
    return r;
}
__device__ __forceinline__ float2 unpk(unsigned long long v) {
    float2 r;
    asm("mov.b64 {%0, %1}, %2;" : "=f"(r.x), "=f"(r.y) : "l"(v));
    return r;
}

// ======================= setup kernels ====================================
__global__ void k_hist(const int* __restrict__ edst) {
    int e = blockIdx.x * blockDim.x + threadIdx.x;
    if (e < EE) atomicAdd(&g_deg[edst[e]], 1);
}

__global__ void k_scan_partial() {
    __shared__ int sh[32];
    int tid = threadIdx.x;
    int i = blockIdx.x * 1024 + tid;
    int v = (i < NN) ? g_deg[i] : 0;
#pragma unroll
    for (int o = 16; o; o >>= 1) v += __shfl_xor_sync(0xffffffffu, v, o);
    if ((tid & 31) == 0) sh[tid >> 5] = v;
    __syncthreads();
    if (tid < 32) {
        int t = sh[tid];
#pragma unroll
        for (int o = 16; o; o >>= 1) t += __shfl_xor_sync(0xffffffffu, t, o);
        if (tid == 0) g_bsum[blockIdx.x] = t;
    }
}

__global__ void k_scan_bsum() {
    __shared__ int sh[64];
    int tid = threadIdx.x;
    int v = (tid < NCHUNK) ? g_bsum[tid] : 0;
    sh[tid] = v;
    __syncthreads();
    for (int off = 1; off < 64; off <<= 1) {
        int t = (tid >= off) ? sh[tid - off] : 0;
        __syncthreads();
        sh[tid] += t;
        __syncthreads();
    }
    if (tid < NCHUNK) g_bsum[tid] = sh[tid] - v;   // exclusive
    if (tid == 0) g_ptr[NN] = EE;
}

__global__ void k_scan_final() {
    __shared__ int sh[32];
    int tid = threadIdx.x, lane = tid & 31, wid = tid >> 5;
    int i = blockIdx.x * 1024 + tid;
    int v = (i < NN) ? g_deg[i] : 0;
    int incl = v;
#pragma unroll
    for (int o = 1; o < 32; o <<= 1) {
        int t = __shfl_up_sync(0xffffffffu, incl, o);
        if (lane >= o) incl += t;
    }
    if (lane == 31) sh[wid] = incl;
    __syncthreads();
    if (wid == 0) {
        int t = sh[lane];
#pragma unroll
        for (int o = 1; o < 32; o <<= 1) {
            int u = __shfl_up_sync(0xffffffffu, t, o);
            if (lane >= o) t += u;
        }
        sh[lane] = t;
    }
    __syncthreads();
    int base = g_bsum[blockIdx.x] + (wid ? sh[wid - 1] : 0);
    if (i < NN) g_ptr[i] = base + incl - v;
}

__global__ void k_scatter(const int* __restrict__ edst) {
    int e = blockIdx.x * blockDim.x + threadIdx.x;
    if (e >= EE) return;
    int d = edst[e];
    int pos = atomicAdd(&g_cur[d], 1);
    g_eid[g_ptr[d] + pos] = e;
}

__global__ void k_loopmean(const float* __restrict__ eattr) {
    int gw = (blockIdx.x * blockDim.x + threadIdx.x) >> 5;
    int lane = threadIdx.x & 31;
    if (gw >= NN) return;
    int beg = g_ptr[gw], end = g_ptr[gw + 1];
    float acc = 0.f;
    for (int t = beg; t < end; t++)
        acc += eattr[(size_t)g_eid[t] * ED + lane];
    g_loopattr[(size_t)gw * ED + lane] = acc / fmaxf((float)(end - beg), 1.f);
}

// ======================= mma.sync bf16x3 node GEMM (dual weight-set) ======
// Computes BOTH: out0 = A@W0 + b0 and out1 = A@W1 + b1 in one CTA, sharing
// the converted A tile and A fragments. grid (ceil(M/128), Nc/64).
// CTA 128x64, K-chunk 32, 8 warps 4(M)x2(N), warp tile 32x32 per z.
#define STRA 20   // A smem row stride in uint32 (40 bf16)
#define STRB 36   // B smem row stride in uint32 (72 bf16)

template <int KTOT>
__global__ void __launch_bounds__(256, 2)
k_mma_nodeZ(const float* __restrict__ A,
            const float* __restrict__ W0, const float* __restrict__ bias0, float* __restrict__ out0,
            const float* __restrict__ W1, const float* __restrict__ bias1, float* __restrict__ out1,
            int M, int Nc) {
    __shared__ __align__(16) uint32_t sAhi[128 * STRA];
    __shared__ __align__(16) uint32_t sAlo[128 * STRA];
    __shared__ __align__(16) uint32_t sBhi[2][32 * STRB];
    __shared__ __align__(16) uint32_t sBlo[2][32 * STRB];

    int tid = threadIdx.x, lane = tid & 31, w = tid >> 5;
    int wm = w & 3, wn = w >> 2;
    int row0 = blockIdx.x * 128, c0 = blockIdx.y * 64;

    uint32_t aHiB = smem_u32(sAhi), aLoB = smem_u32(sAlo);
    uint32_t bHiB0 = smem_u32(sBhi[0]), bLoB0 = smem_u32(sBlo[0]);

    float acc[2][2][4][4];   // [z][ii][j][q]
#pragma unroll
    for (int z = 0; z < 2; z++)
#pragma unroll
        for (int i = 0; i < 2; i++)
#pragma unroll
            for (int j = 0; j < 4; j++)
#pragma unroll
                for (int q = 0; q < 4; q++) acc[z][i][j][q] = 0.f;

    for (int k0 = 0; k0 < KTOT; k0 += 32) {
        // ---- A chunk 128x32 f32 -> hi/lo bf16 smem (shared by both z)
#pragma unroll
        for (int t = 0; t < 4; t++) {
            int idx = tid + t * 256;
            int r = idx >> 3, c4 = (idx & 7) * 4;
            float4 v = make_float4(0.f, 0.f, 0.f, 0.f);
            if (row0 + r < M)
                v = *(const float4*)&A[(size_t)(row0 + r) * KTOT + k0 + c4];
            uint32_t h01 = packbf(v.x, v.y);
            uint32_t h23 = packbf(v.z, v.w);
            float r0 = v.x - __uint_as_float(h01 << 16);
            float r1 = v.y - __uint_as_float(h01 & 0xffff0000u);
            float r2 = v.z - __uint_as_float(h23 << 16);
            float r3 = v.w - __uint_as_float(h23 & 0xffff0000u);
            int o = r * STRA + (c4 >> 1);
            sAhi[o] = h01; sAhi[o + 1] = h23;
            sAlo[o] = packbf(r0, r1); sAlo[o + 1] = packbf(r2, r3);
        }
        // ---- B chunks 32x64 f32 for z=0,1 -> hi/lo bf16 smem
#pragma unroll
        for (int t = 0; t < 4; t++) {
            int idx = tid + t * 256;           // 0..1023
            int z = idx >> 9;                  // 512 per z
            int rem = idx & 511;
            int r = rem >> 4, c4 = (rem & 15) * 4;
            const float* Wz = z ? W1 : W0;
            float4 v = *(const float4*)&Wz[(size_t)(k0 + r) * Nc + c0 + c4];
            uint32_t h01 = packbf(v.x, v.y);
            uint32_t h23 = packbf(v.z, v.w);
            float r0 = v.x - __uint_as_float(h01 << 16);
            float r1 = v.y - __uint_as_float(h01 & 0xffff0000u);
            float r2 = v.z - __uint_as_float(h23 << 16);
            float r3 = v.w - __uint_as_float(h23 & 0xffff0000u);
            int o = r * STRB + (c4 >> 1);
            sBhi[z][o] = h01; sBhi[z][o + 1] = h23;
            sBlo[z][o] = packbf(r0, r1); sBlo[z][o + 1] = packbf(r2, r3);
        }
        __syncthreads();

#pragma unroll
        for (int s = 0; s < 2; s++) {
            // A fragments, shared by both z
            uint32_t aH[2][4], aL[2][4];
#pragma unroll
            for (int ii = 0; ii < 2; ii++) {
                int tile = lane >> 3, rr = lane & 7;
                int row = wm * 32 + ii * 16 + (tile & 1) * 8 + rr;
                int kk = s * 16 + (tile >> 1) * 8;
                uint32_t off = (uint32_t)(row * STRA) * 4u + (uint32_t)kk * 2u;
                ldm_x4(aH[ii], aHiB + off);
                ldm_x4(aL[ii], aLoB + off);
            }
            // B fragments per z via x4.trans (covers 2 cols x 2 k-halves)
            int q = lane >> 3, rr = lane & 7;
            int krow = s * 16 + (q & 1) * 8 + rr;
#pragma unroll
            for (int z = 0; z < 2; z++) {
                uint32_t zb = (uint32_t)(z * 32 * STRB * 4);
                uint32_t bH4[2][4], bL4[2][4];
#pragma unroll
                for (int j2 = 0; j2 < 2; j2++) {
                    int ncol = wn * 32 + (j2 * 2 + (q >> 1)) * 8;
                    uint32_t off = (uint32_t)(krow * STRB) * 4u + (uint32_t)ncol * 2u;
                    ldm_x4t(bH4[j2], bHiB0 + zb + off);
                    ldm_x4t(bL4[j2], bLoB0 + zb + off);
                }
#pragma unroll
                for (int ii = 0; ii < 2; ii++)
#pragma unroll
                    for (int j = 0; j < 4; j++) {
                        uint32_t bh0 = bH4[j >> 1][(j & 1) * 2];
                        uint32_t bh1 = bH4[j >> 1][(j & 1) * 2 + 1];
                        uint32_t bl0 = bL4[j >> 1][(j & 1) * 2];
                        uint32_t bl1 = bL4[j >> 1][(j & 1) * 2 + 1];
                        mma_bf16(acc[z][ii][j], aH[ii], bh0, bh1);
                        mma_bf16(acc[z][ii][j], aH[ii], bl0, bl1);
                        mma_bf16(acc[z][ii][j], aL[ii], bh0, bh1);
                    }
            }
        }
        __syncthreads();
    }

    // ---- epilogue (both z)
    int g = lane >> 2, tg = lane & 3;
#pragma unroll
    for (int z = 0; z < 2; z++) {
        const float* bias = z ? bias1 : bias0;
        float* out        = z ? out1 : out0;
#pragma unroll
        for (int i = 0; i < 2; i++) {
            int r1 = row0 + wm * 32 + i * 16 + g;
            int r2 = r1 + 8;
#pragma unroll
            for (int j = 0; j < 4; j++) {
                int col = c0 + wn * 32 + j * 8 + tg * 2;
                float2 bv = *(const float2*)&bias[col];
                if (r1 < M) {
                    float2 o = make_float2(acc[z][i][j][0] + bv.x, acc[z][i][j][1] + bv.y);
                    *(float2*)&out[(size_t)r1 * Nc + col] = o;
                }
                if (r2 < M) {
                    float2 o = make_float2(acc[z][i][j][2] + bv.x, acc[z][i][j][3] + bv.y);
                    *(float2*)&out[(size_t)r2 * Nc + col] = o;
                }
            }
        }
    }
}

// ======================= fused edge-score GEMM (no atomics) ===============
// 64 edges x ALL C cols per block. Lane owns cols {lane, lane+32, ...} so all
// smem/gmem accesses are conflict-free / coalesced. f32x2 packs edge pairs.
template <int C>
__global__ void __launch_bounds__(256)
k_score2(const float* __restrict__ eattr, const float* __restrict__ We,
         const int* __restrict__ esrc, const int* __restrict__ edst,
         const float* __restrict__ att,
         const float* __restrict__ xl, const float* __restrict__ xr) {
    constexpr int CPL = C / 32;               // cols per lane
    __shared__ uint32_t AsU[ED][64];          // [k][edge] fp32 bits, 8KB
    __shared__ float Bs[ED][C];               // We [k][col]
    __shared__ int ssrc[64], sdst[64];
    int tid = threadIdx.x, w = tid >> 5, lane = tid & 31;
    int r0 = blockIdx.x * 64;

    for (int idx = tid; idx < 64 * 8; idx += 256) {
        int e = idx >> 3, c4 = (idx & 7) * 4;
        float4 v = make_float4(0.f, 0.f, 0.f, 0.f);
        if (r0 + e < EE) v = *(const float4*)&eattr[(size_t)(r0 + e) * ED + c4];
        AsU[c4 + 0][e] = __float_as_uint(v.x);
        AsU[c4 + 1][e] = __float_as_uint(v.y);
        AsU[c4 + 2][e] = __float_as_uint(v.z);
        AsU[c4 + 3][e] = __float_as_uint(v.w);
    }
    for (int idx = tid; idx < ED * (C / 4); idx += 256) {
        int k = idx / (C / 4), c = (idx % (C / 4)) * 4;
        *(float4*)&Bs[k][c] = *(const float4*)&We[(size_t)k * C + c];
    }
    if (tid < 64) {
        int e = r0 + tid;
        ssrc[tid] = (e < EE) ? esrc[e] : 0;
        sdst[tid] = (e < EE) ? edst[e] : 0;
    }
    __syncthreads();

    unsigned long long acc2[4][CPL];
#pragma unroll
    for (int p = 0; p < 4; p++)
#pragma unroll
        for (int j = 0; j < CPL; j++) acc2[p][j] = 0ull;

#pragma unroll
    for (int k = 0; k < ED; k++) {
        ulonglong2 aA = *(const ulonglong2*)&AsU[k][w * 8];
        ulonglong2 aB = *(const ulonglong2*)&AsU[k][w * 8 + 4];
        unsigned long long a[4] = {aA.x, aA.y, aB.x, aB.y};
#pragma unroll
        for (int j = 0; j < CPL; j++) {
            unsigned long long b = dupf(Bs[k][lane + 32 * j]);  // conflict-free
#pragma unroll
            for (int p = 0; p < 4; p++)
                acc2[p][j] = ffma2(a[p], b, acc2[p][j]);
        }
    }

    float attv[CPL];
#pragma unroll
    for (int j = 0; j < CPL; j++) attv[j] = att[lane + 32 * j];

#pragma unroll
    for (int p = 0; p < 4; p++) {
        int e0i = w * 8 + 2 * p, e1i = e0i + 1;
        const float* xl0 = &xl[(size_t)ssrc[e0i] * C + lane];
        const float* xr0 = &xr[(size_t)sdst[e0i] * C + lane];
        const float* xl1 = &xl[(size_t)ssrc[e1i] * C + lane];
        const float* xr1 = &xr[(size_t)sdst[e1i] * C + lane];
        float pe0 = 0.f, pe1 = 0.f;
#pragma unroll
        for (int j = 0; j < CPL; j++) {
            float2 v = unpk(acc2[p][j]);
            float t0 = v.x + xl0[32 * j] + xr0[32 * j]; t0 = t0 > 0.f ? t0 : 0.2f * t0;
            float t1 = v.y + xl1[32 * j] + xr1[32 * j]; t1 = t1 > 0.f ? t1 : 0.2f * t1;
            pe0 += attv[j] * t0;
            pe1 += attv[j] * t1;
        }
#pragma unroll
        for (int o = 16; o; o >>= 1) {
            pe0 += __shfl_xor_sync(0xffffffffu, pe0, o);
            pe1 += __shfl_xor_sync(0xffffffffu, pe1, o);
        }
        if (lane == 0) {
            if (r0 + e0i < EE) g_escore[r0 + e0i] = pe0;
            if (r0 + e1i < EE) g_escore[r0 + e1i] = pe1;
        }
    }
}

// ======================= self-loop score per node =========================
template <int C>
__global__ void k_eself(const float* __restrict__ We, const float* __restrict__ att,
                        const float* __restrict__ xl, const float* __restrict__ xr) {
    int gw = (blockIdx.x * blockDim.x + threadIdx.x) >> 5;
    int lane = threadIdx.x & 31;
    if (gw >= NN) return;
    float la = g_loopattr[(size_t)gw * ED + lane];
    float acc = 0.f;
#pragma unroll
    for (int jj = 0; jj < C / 32; jj++) {
        int j = jj * 32 + lane;
        float v = xl[(size_t)gw * C + j] + xr[(size_t)gw * C + j];
#pragma unroll
        for (int k = 0; k < ED; k++)
            v += __shfl_sync(0xffffffffu, la, k) * We[k * C + j];
        v = v > 0.f ? v : 0.2f * v;
        acc += att[j] * v;
    }
#pragma unroll
    for (int off = 16; off; off >>= 1) acc += __shfl_xor_sync(0xffffffffu, acc, off);
    if (lane == 0) g_eself[gw] = acc;
}

// ======================= softmax + aggregation (warp/node) ================
template <int C>
__global__ void k_aggregate(const int* __restrict__ esrc,
                            const float* __restrict__ xl,
                            const float* __restrict__ bias,
                            float* __restrict__ outp) {
    int gw = (blockIdx.x * blockDim.x + threadIdx.x) >> 5;
    int lane = threadIdx.x & 31;
    if (gw >= NN) return;
    int beg = g_ptr[gw], end = g_ptr[gw + 1];

    float m = g_eself[gw];
    for (int t = beg + lane; t < end; t += 32) m = fmaxf(m, g_escore[g_eid[t]]);
#pragma unroll
    for (int off = 16; off; off >>= 1) m = fmaxf(m, __shfl_xor_sync(0xffffffffu, m, off));

    float4 acc[C / 128];
#pragma unroll
    for (int jj = 0; jj < C / 128; jj++) acc[jj] = make_float4(0.f, 0.f, 0.f, 0.f);
    float denom = 0.f;

    for (int t = beg; t < end; t++) {
        int eid = g_eid[t];
        float w = expf(g_escore[eid] - m);
        int s = esrc[eid];
        denom += w;
#pragma unroll
        for (int jj = 0; jj < C / 128; jj++) {
            float4 x4 = *(const float4*)&xl[(size_t)s * C + jj * 128 + lane * 4];
            acc[jj].x += w * x4.x; acc[jj].y += w * x4.y;
            acc[jj].z += w * x4.z; acc[jj].w += w * x4.w;
        }
    }
    float ws = expf(g_eself[gw] - m);
    denom += ws;
#pragma unroll
    for (int jj = 0; jj < C / 128; jj++) {
        float4 x4 = *(const float4*)&xl[(size_t)gw * C + jj * 128 + lane * 4];
        acc[jj].x += ws * x4.x; acc[jj].y += ws * x4.y;
        acc[jj].z += ws * x4.z; acc[jj].w += ws * x4.w;
    }

    float inv = 1.f / denom;
#pragma unroll
    for (int jj = 0; jj < C / 128; jj++) {
        int c = jj * 128 + lane * 4;
        float4 b4 = *(const float4*)&bias[c];
        float4 o;
        o.x = fmaxf(acc[jj].x * inv + b4.x, 0.f);
        o.y = fmaxf(acc[jj].y * inv + b4.y, 0.f);
        o.z = fmaxf(acc[jj].z * inv + b4.z, 0.f);
        o.w = fmaxf(acc[jj].w * inv + b4.w, 0.f);
        *(float4*)&outp[(size_t)gw * C + c] = o;
    }
}

// ======================= global mean pool =================================
#define NPB 196
__global__ void k_pool2(const int* __restrict__ batch) {
    int tid = threadIdx.x;                 // 128 threads = H2 columns
    int n0 = blockIdx.x * NPB;
    int n1 = min(n0 + NPB, NN);
    if (n0 >= n1) return;
    int curg = batch[n0];
    float acc = 0.f;
    for (int n = n0; n < n1; n++) {
        int g = batch[n];
        if (g != curg) {
            atomicAdd(&g_pool[curg * H2 + tid], acc);
            acc = 0.f;
            curg = g;
        }
        acc += g_h2[(size_t)n * H2 + tid];
    }
    atomicAdd(&g_pool[curg * H2 + tid], acc);
}

// ======================= MLP head =========================================
__device__ __forceinline__ int lowerb(const int* b, int val) {
    int lo = 0, hi = NN;
    while (lo < hi) { int m = (lo + hi) >> 1; if (b[m] < val) lo = m + 1; else hi = m; }
    return lo;
}

__global__ void k_head(const int* __restrict__ batch,
                       const float* __restrict__ Wd1, const float* __restrict__ bd1,
                       const float* __restrict__ gma, const float* __restrict__ bta,
                       const float* __restrict__ mean, const float* __restrict__ var,
                       const float* __restrict__ Wd2, const float* __restrict__ bd2,
                       float* __restrict__ out) {
    __shared__ float sp[GG * H2];
    __shared__ float sh[GG * HD];
    __shared__ float scnt[GG];
    int tid = threadIdx.x;
    if (tid < GG)
        scnt[tid] = (float)(lowerb(batch, tid + 1) - lowerb(batch, tid));
    __syncthreads();
    for (int idx = tid; idx < GG * H2; idx += blockDim.x) {
        int g = idx / H2;
        sp[idx] = g_pool[idx] / fmaxf(scnt[g], 1.f);
    }
    __syncthreads();
    for (int idx = tid; idx < GG * HD; idx += blockDim.x) {
        int g = idx / HD, h = idx - g * HD;
        float a = bd1[h];
        for (int k = 0; k < H2; k++) a += sp[g * H2 + k] * Wd1[k * HD + h];
        a = (a - mean[h]) / sqrtf(var[h] + 1e-5f) * gma[h] + bta[h];
        a = a > 0.f ? a : 0.1f * a;
        sh[idx] = a;
    }
    __syncthreads();
    for (int idx = tid; idx < GG * OUTD; idx += blockDim.x) {
        int g = idx / OUTD, o = idx - g * OUTD;
        float a = bd2[o];
        for (int k = 0; k < HD; k++) a += sh[g * HD + k] * Wd2[k * OUTD + o];
        out[idx] = a;
    }
}

// ======================= launcher =========================================
extern "C" void kernel_launch(void* const* d_in, const int* in_sizes, int n_in,
                              void* d_out, int out_size) {
    const float* node_attr = (const float*)d_in[0];
    const float* edge_attr = (const float*)d_in[1];
    const int*   esrc      = (const int*)d_in[2];
    const int*   edst      = (const int*)d_in[3];
    const int*   batch     = (const int*)d_in[4];
    const float *Wl1 = (const float*)d_in[5],  *bl1 = (const float*)d_in[6];
    const float *Wr1 = (const float*)d_in[7],  *br1 = (const float*)d_in[8];
    const float *We1 = (const float*)d_in[9],  *att1 = (const float*)d_in[10], *b1 = (const float*)d_in[11];
    const float *Wl2 = (const float*)d_in[12], *bl2 = (const float*)d_in[13];
    const float *Wr2 = (const float*)d_in[14], *br2 = (const float*)d_in[15];
    const float *We2 = (const float*)d_in[16], *att2 = (const float*)d_in[17], *b2 = (const float*)d_in[18];
    const float *Wd1 = (const float*)d_in[19], *bd1 = (const float*)d_in[20];
    const float *gma = (const float*)d_in[21], *bta = (const float*)d_in[22];
    const float *mean = (const float*)d_in[23], *var = (const float*)d_in[24];
    const float *Wd2 = (const float*)d_in[25], *bd2 = (const float*)d_in[26];
    float* out = (float*)d_out;

    float *p_xl, *p_xr, *p_h1, *p_h2, *p_pool;
    int *p_deg, *p_cur;
    cudaGetSymbolAddress((void**)&p_xl, g_xl);
    cudaGetSymbolAddress((void**)&p_xr, g_xr);
    cudaGetSymbolAddress((void**)&p_h1, g_h1);
    cudaGetSymbolAddress((void**)&p_h2, g_h2);
    cudaGetSymbolAddress((void**)&p_pool, g_pool);
    cudaGetSymbolAddress((void**)&p_deg, g_deg);
    cudaGetSymbolAddress((void**)&p_cur, g_cur);

    cudaMemsetAsync(p_deg, 0, NN * sizeof(int), 0);
    cudaMemsetAsync(p_cur, 0, NN * sizeof(int), 0);
    cudaMemsetAsync(p_pool, 0, GG * H2 * sizeof(float), 0);

    int nodeWB = (NN * 32 + 255) / 256;   // warp-per-node blocks
    int rowT = (NN + 127) / 128;          // 391

    // setup + layer-1 node GEMM interleaved (GEMM depends only on inputs)
    k_hist<<<(EE + 255) / 256, 256>>>(edst);
    k_scan_partial<<<NCHUNK, 1024>>>();
    k_scan_bsum<<<1, 64>>>();
    k_mma_nodeZ<DIN><<<dim3(rowT, H1 / 64), 256>>>(
        node_attr, Wl1, bl1, p_xl, Wr1, br1, p_xr, NN, H1);
    k_scan_final<<<NCHUNK, 1024>>>();
    k_scatter<<<(EE + 255) / 256, 256>>>(edst);
    k_loopmean<<<nodeWB, 256>>>(edge_attr);

    // ---------------- layer 1 ----------------
    k_score2<H1><<<(EE + 63) / 64, 256>>>(edge_attr, We1, esrc, edst, att1, p_xl, p_xr);
    k_eself<H1><<<nodeWB, 256>>>(We1, att1, p_xl, p_xr);
    k_aggregate<H1><<<nodeWB, 256>>>(esrc, p_xl, b1, p_h1);

    // ---------------- layer 2 ----------------
    k_mma_nodeZ<H1><<<dim3(rowT, H2 / 64), 256>>>(
        p_h1, Wl2, bl2, p_xl, Wr2, br2, p_xr, NN, H2);
    k_score2<H2><<<(EE + 63) / 64, 256>>>(edge_attr, We2, esrc, edst, att2, p_xl, p_xr);
    k_eself<H2><<<nodeWB, 256>>>(We2, att2, p_xl, p_xr);
    k_aggregate<H2><<<nodeWB, 256>>>(esrc, p_xl, b2, p_h2);

    // ---------------- pool + head ----------------
    k_pool2<<<(NN + NPB - 1) / NPB, 128>>>(batch);
    k_head<<<1, 512>>>(batch, Wd1, bd1, gma, bta, mean, var, Wd2, bd2, out);
}

// round 8
// speedup vs baseline: 1.2130x; 1.1560x over previous
#include <cuda_runtime.h>
#include <cuda_bf16.h>
#include <math.h>
#include <stdint.h>

#define NN   50000
#define EE   500000
#define GG   64
#define DIN  128
#define ED   32
#define H1   256
#define H2   128
#define HD   64
#define OUTD 8
#define NCHUNK 49   // ceil(NN/1024)

// ---------------- scratch (device globals; no allocation allowed) ----------
__device__ float g_xl[(size_t)NN * H1];
__device__ float g_xr[(size_t)NN * H1];
__device__ float g_h1[(size_t)NN * H1];
__device__ float g_h2[(size_t)NN * H2];
__device__ float g_escore[EE];
__device__ float g_eself[NN];
__device__ float g_loopattr[(size_t)NN * ED];
__device__ int   g_deg[NN];
__device__ int   g_ptr[NN + 1];
__device__ int   g_cur[NN];
__device__ int   g_eid[EE];
__device__ int   g_bsum[64];
__device__ float g_pool[GG * H2];

// ======================= helpers ==========================================
__device__ __forceinline__ uint32_t smem_u32(const void* p) {
    uint32_t a;
    asm("{ .reg .u64 t; cvta.to.shared.u64 t, %1; cvt.u32.u64 %0, t; }" : "=r"(a) : "l"(p));
    return a;
}
// pack two f32 (k-order: lo_k first) into bf16x2 word (low half = lo_k)
__device__ __forceinline__ uint32_t packbf(float lo_k, float hi_k) {
    uint32_t r;
    asm("cvt.rn.bf16x2.f32 %0, %1, %2;" : "=r"(r) : "f"(hi_k), "f"(lo_k));
    return r;
}
__device__ __forceinline__ void ldm_x4(uint32_t (&r)[4], uint32_t addr) {
    asm volatile("ldmatrix.sync.aligned.m8n8.x4.shared.b16 {%0,%1,%2,%3}, [%4];"
        : "=r"(r[0]), "=r"(r[1]), "=r"(r[2]), "=r"(r[3]) : "r"(addr));
}
__device__ __forceinline__ void ldm_x4t(uint32_t (&r)[4], uint32_t addr) {
    asm volatile("ldmatrix.sync.aligned.m8n8.x4.trans.shared.b16 {%0,%1,%2,%3}, [%4];"
        : "=r"(r[0]), "=r"(r[1]), "=r"(r[2]), "=r"(r[3]) : "r"(addr));
}
__device__ __forceinline__ void mma_bf16(float (&c)[4], const uint32_t (&a)[4],
                                         uint32_t b0, uint32_t b1) {
    asm volatile("mma.sync.aligned.m16n8k16.row.col.f32.bf16.bf16.f32 "
        "{%0,%1,%2,%3},{%4,%5,%6,%7},{%8,%9},{%0,%1,%2,%3};"
        : "+f"(c[0]), "+f"(c[1]), "+f"(c[2]), "+f"(c[3])
        : "r"(a[0]), "r"(a[1]), "r"(a[2]), "r"(a[3]), "r"(b0), "r"(b1));
}
// convert float4 -> hi/lo bf16x2 pair words
__device__ __forceinline__ void cvt4(const float4& v, uint32_t& h01, uint32_t& h23,
                                     uint32_t& l01, uint32_t& l23) {
    h01 = packbf(v.x, v.y);
    h23 = packbf(v.z, v.w);
    float r0 = v.x - __uint_as_float(h01 << 16);
    float r1 = v.y - __uint_as_float(h01 & 0xffff0000u);
    float r2 = v.z - __uint_as_float(h23 << 16);
    float r3 = v.w - __uint_as_float(h23 & 0xffff0000u);
    l01 = packbf(r0, r1);
    l23 = packbf(r2, r3);
}

// ======================= setup kernels ====================================
__global__ void k_hist(const int* __restrict__ edst) {
    int e = blockIdx.x * blockDim.x + threadIdx.x;
    if (e < EE) atomicAdd(&g_deg[edst[e]], 1);
}

__global__ void k_scan_partial() {
    __shared__ int sh[32];
    int tid = threadIdx.x;
    int i = blockIdx.x * 1024 + tid;
    int v = (i < NN) ? g_deg[i] : 0;
#pragma unroll
    for (int o = 16; o; o >>= 1) v += __shfl_xor_sync(0xffffffffu, v, o);
    if ((tid & 31) == 0) sh[tid >> 5] = v;
    __syncthreads();
    if (tid < 32) {
        int t = sh[tid];
#pragma unroll
        for (int o = 16; o; o >>= 1) t += __shfl_xor_sync(0xffffffffu, t, o);
        if (tid == 0) g_bsum[blockIdx.x] = t;
    }
}

__global__ void k_scan_bsum() {
    __shared__ int sh[64];
    int tid = threadIdx.x;
    int v = (tid < NCHUNK) ? g_bsum[tid] : 0;
    sh[tid] = v;
    __syncthreads();
    for (int off = 1; off < 64; off <<= 1) {
        int t = (tid >= off) ? sh[tid - off] : 0;
        __syncthreads();
        sh[tid] += t;
        __syncthreads();
    }
    if (tid < NCHUNK) g_bsum[tid] = sh[tid] - v;   // exclusive
    if (tid == 0) g_ptr[NN] = EE;
}

__global__ void k_scan_final() {
    __shared__ int sh[32];
    int tid = threadIdx.x, lane = tid & 31, wid = tid >> 5;
    int i = blockIdx.x * 1024 + tid;
    int v = (i < NN) ? g_deg[i] : 0;
    int incl = v;
#pragma unroll
    for (int o = 1; o < 32; o <<= 1) {
        int t = __shfl_up_sync(0xffffffffu, incl, o);
        if (lane >= o) incl += t;
    }
    if (lane == 31) sh[wid] = incl;
    __syncthreads();
    if (wid == 0) {
        int t = sh[lane];
#pragma unroll
        for (int o = 1; o < 32; o <<= 1) {
            int u = __shfl_up_sync(0xffffffffu, t, o);
            if (lane >= o) t += u;
        }
        sh[lane] = t;
    }
    __syncthreads();
    int base = g_bsum[blockIdx.x] + (wid ? sh[wid - 1] : 0);
    if (i < NN) g_ptr[i] = base + incl - v;
}

__global__ void k_scatter(const int* __restrict__ edst) {
    int e = blockIdx.x * blockDim.x + threadIdx.x;
    if (e >= EE) return;
    int d = edst[e];
    int pos = atomicAdd(&g_cur[d], 1);
    g_eid[g_ptr[d] + pos] = e;
}

__global__ void k_loopmean(const float* __restrict__ eattr) {
    int gw = (blockIdx.x * blockDim.x + threadIdx.x) >> 5;
    int lane = threadIdx.x & 31;
    if (gw >= NN) return;
    int beg = g_ptr[gw], end = g_ptr[gw + 1];
    float acc = 0.f;
    for (int t = beg; t < end; t++)
        acc += eattr[(size_t)g_eid[t] * ED + lane];
    g_loopattr[(size_t)gw * ED + lane] = acc / fmaxf((float)(end - beg), 1.f);
}

// ======================= mma.sync bf16x3 node GEMM (dual weight-set) ======
#define STRA 20   // A smem row stride in uint32 (40 bf16)
#define STRB 36   // B smem row stride in uint32 (72 bf16)

template <int KTOT>
__global__ void __launch_bounds__(256, 2)
k_mma_nodeZ(const float* __restrict__ A,
            const float* __restrict__ W0, const float* __restrict__ bias0, float* __restrict__ out0,
            const float* __restrict__ W1, const float* __restrict__ bias1, float* __restrict__ out1,
            int M, int Nc) {
    __shared__ __align__(16) uint32_t sAhi[128 * STRA];
    __shared__ __align__(16) uint32_t sAlo[128 * STRA];
    __shared__ __align__(16) uint32_t sBhi[2][32 * STRB];
    __shared__ __align__(16) uint32_t sBlo[2][32 * STRB];

    int tid = threadIdx.x, lane = tid & 31, w = tid >> 5;
    int wm = w & 3, wn = w >> 2;
    int row0 = blockIdx.x * 128, c0 = blockIdx.y * 64;

    uint32_t aHiB = smem_u32(sAhi), aLoB = smem_u32(sAlo);
    uint32_t bHiB0 = smem_u32(sBhi[0]), bLoB0 = smem_u32(sBlo[0]);

    float acc[2][2][4][4];   // [z][ii][j][q]
#pragma unroll
    for (int z = 0; z < 2; z++)
#pragma unroll
        for (int i = 0; i < 2; i++)
#pragma unroll
            for (int j = 0; j < 4; j++)
#pragma unroll
                for (int q = 0; q < 4; q++) acc[z][i][j][q] = 0.f;

    for (int k0 = 0; k0 < KTOT; k0 += 32) {
#pragma unroll
        for (int t = 0; t < 4; t++) {
            int idx = tid + t * 256;
            int r = idx >> 3, c4 = (idx & 7) * 4;
            float4 v = make_float4(0.f, 0.f, 0.f, 0.f);
            if (row0 + r < M)
                v = *(const float4*)&A[(size_t)(row0 + r) * KTOT + k0 + c4];
            uint32_t h01, h23, l01, l23;
            cvt4(v, h01, h23, l01, l23);
            int o = r * STRA + (c4 >> 1);
            sAhi[o] = h01; sAhi[o + 1] = h23;
            sAlo[o] = l01; sAlo[o + 1] = l23;
        }
#pragma unroll
        for (int t = 0; t < 4; t++) {
            int idx = tid + t * 256;           // 0..1023
            int z = idx >> 9;                  // 512 per z
            int rem = idx & 511;
            int r = rem >> 4, c4 = (rem & 15) * 4;
            const float* Wz = z ? W1 : W0;
            float4 v = *(const float4*)&Wz[(size_t)(k0 + r) * Nc + c0 + c4];
            uint32_t h01, h23, l01, l23;
            cvt4(v, h01, h23, l01, l23);
            int o = r * STRB + (c4 >> 1);
            sBhi[z][o] = h01; sBhi[z][o + 1] = h23;
            sBlo[z][o] = l01; sBlo[z][o + 1] = l23;
        }
        __syncthreads();

#pragma unroll
        for (int s = 0; s < 2; s++) {
            uint32_t aH[2][4], aL[2][4];
#pragma unroll
            for (int ii = 0; ii < 2; ii++) {
                int tile = lane >> 3, rr = lane & 7;
                int row = wm * 32 + ii * 16 + (tile & 1) * 8 + rr;
                int kk = s * 16 + (tile >> 1) * 8;
                uint32_t off = (uint32_t)(row * STRA) * 4u + (uint32_t)kk * 2u;
                ldm_x4(aH[ii], aHiB + off);
                ldm_x4(aL[ii], aLoB + off);
            }
            int q = lane >> 3, rr = lane & 7;
            int krow = s * 16 + (q & 1) * 8 + rr;
#pragma unroll
            for (int z = 0; z < 2; z++) {
                uint32_t zb = (uint32_t)(z * 32 * STRB * 4);
                uint32_t bH4[2][4], bL4[2][4];
#pragma unroll
                for (int j2 = 0; j2 < 2; j2++) {
                    int ncol = wn * 32 + (j2 * 2 + (q >> 1)) * 8;
                    uint32_t off = (uint32_t)(krow * STRB) * 4u + (uint32_t)ncol * 2u;
                    ldm_x4t(bH4[j2], bHiB0 + zb + off);
                    ldm_x4t(bL4[j2], bLoB0 + zb + off);
                }
#pragma unroll
                for (int ii = 0; ii < 2; ii++)
#pragma unroll
                    for (int j = 0; j < 4; j++) {
                        uint32_t bh0 = bH4[j >> 1][(j & 1) * 2];
                        uint32_t bh1 = bH4[j >> 1][(j & 1) * 2 + 1];
                        uint32_t bl0 = bL4[j >> 1][(j & 1) * 2];
                        uint32_t bl1 = bL4[j >> 1][(j & 1) * 2 + 1];
                        mma_bf16(acc[z][ii][j], aH[ii], bh0, bh1);
                        mma_bf16(acc[z][ii][j], aH[ii], bl0, bl1);
                        mma_bf16(acc[z][ii][j], aL[ii], bh0, bh1);
                    }
            }
        }
        __syncthreads();
    }

    int g = lane >> 2, tg = lane & 3;
#pragma unroll
    for (int z = 0; z < 2; z++) {
        const float* bias = z ? bias1 : bias0;
        float* out        = z ? out1 : out0;
#pragma unroll
        for (int i = 0; i < 2; i++) {
            int r1 = row0 + wm * 32 + i * 16 + g;
            int r2 = r1 + 8;
#pragma unroll
            for (int j = 0; j < 4; j++) {
                int col = c0 + wn * 32 + j * 8 + tg * 2;
                float2 bv = *(const float2*)&bias[col];
                if (r1 < M) {
                    float2 o = make_float2(acc[z][i][j][0] + bv.x, acc[z][i][j][1] + bv.y);
                    *(float2*)&out[(size_t)r1 * Nc + col] = o;
                }
                if (r2 < M) {
                    float2 o = make_float2(acc[z][i][j][2] + bv.x, acc[z][i][j][3] + bv.y);
                    *(float2*)&out[(size_t)r2 * Nc + col] = o;
                }
            }
        }
    }
}

// ======================= tensorized edge-score kernel =====================
// CTA = 128 edges x ALL C cols. ew = eattr@We via mma.sync bf16x3; epilogue
// gathers xl[src]/xr[dst], applies leaky+att, reduces per-edge via shfl +
// smem atomics. No global atomics.
template <int C>
__global__ void __launch_bounds__(256, 2)
k_score_mma(const float* __restrict__ eattr, const float* __restrict__ We,
            const int* __restrict__ esrc, const int* __restrict__ edst,
            const float* __restrict__ att,
            const float* __restrict__ xl, const float* __restrict__ xr) {
    constexpr int STRC = C / 2 + 4;            // We smem row stride (u32)
    constexpr int ASZ = 128 * STRA * 4;        // 10240
    constexpr int BSZ = 32 * STRC * 4;
    constexpr int OFF_ALO = ASZ;
    constexpr int OFF_BHI = 2 * ASZ;
    constexpr int OFF_BLO = 2 * ASZ + BSZ;
    constexpr int OFF_SRC = 2 * ASZ + 2 * BSZ;
    constexpr int OFF_DST = OFF_SRC + 512;
    constexpr int OFF_ATT = OFF_DST + 512;
    constexpr int OFF_SC  = OFF_ATT + C * 4;

    extern __shared__ char smem[];
    uint32_t sb = smem_u32(smem);
    uint32_t* sAhi = (uint32_t*)smem;
    uint32_t* sAlo = (uint32_t*)(smem + OFF_ALO);
    uint32_t* sBhi = (uint32_t*)(smem + OFF_BHI);
    uint32_t* sBlo = (uint32_t*)(smem + OFF_BLO);
    int* ssrc   = (int*)(smem + OFF_SRC);
    int* sdst   = (int*)(smem + OFF_DST);
    float* satt = (float*)(smem + OFF_ATT);
    float* sscore = (float*)(smem + OFF_SC);

    int tid = threadIdx.x, lane = tid & 31, w = tid >> 5;
    int wm = w & 3, wn = w >> 2;
    int r0 = blockIdx.x * 128;

    // ---- A: eattr 128x32 -> hi/lo bf16
#pragma unroll
    for (int t = 0; t < 4; t++) {
        int idx = tid + t * 256;
        int r = idx >> 3, c4 = (idx & 7) * 4;
        float4 v = make_float4(0.f, 0.f, 0.f, 0.f);
        if (r0 + r < EE) v = *(const float4*)&eattr[(size_t)(r0 + r) * ED + c4];
        uint32_t h01, h23, l01, l23;
        cvt4(v, h01, h23, l01, l23);
        int o = r * STRA + (c4 >> 1);
        sAhi[o] = h01; sAhi[o + 1] = h23;
        sAlo[o] = l01; sAlo[o + 1] = l23;
    }
    // ---- B: We 32xC -> hi/lo bf16
    for (int idx = tid; idx < 32 * (C / 4); idx += 256) {
        int r = idx / (C / 4), c4 = (idx % (C / 4)) * 4;
        float4 v = *(const float4*)&We[(size_t)r * C + c4];
        uint32_t h01, h23, l01, l23;
        cvt4(v, h01, h23, l01, l23);
        int o = r * STRC + (c4 >> 1);
        sBhi[o] = h01; sBhi[o + 1] = h23;
        sBlo[o] = l01; sBlo[o + 1] = l23;
    }
    if (tid < 128) {
        int e = r0 + tid;
        ssrc[tid] = (e < EE) ? esrc[e] : 0;
        sdst[tid] = (e < EE) ? edst[e] : 0;
        sscore[tid] = 0.f;
    }
    for (int c = tid; c < C; c += 256) satt[c] = att[c];
    __syncthreads();

    // ---- A fragments (K=32 fixed, loaded once)
    uint32_t aH[2][2][4], aL[2][2][4];   // [s][ii]
#pragma unroll
    for (int s = 0; s < 2; s++)
#pragma unroll
        for (int ii = 0; ii < 2; ii++) {
            int tile = lane >> 3, rr = lane & 7;
            int row = wm * 32 + ii * 16 + (tile & 1) * 8 + rr;
            int kk = s * 16 + (tile >> 1) * 8;
            uint32_t off = (uint32_t)(row * STRA) * 4u + (uint32_t)kk * 2u;
            ldm_x4(aH[s][ii], sb + off);
            ldm_x4(aL[s][ii], sb + OFF_ALO + off);
        }

    int g = lane >> 2, tg = lane & 3;
    float sc[2][2] = {{0.f, 0.f}, {0.f, 0.f}};   // [ii][rowhalf]

#pragma unroll
    for (int nb = 0; nb < C / 64; nb++) {
        float acc[2][4][4];
#pragma unroll
        for (int ii = 0; ii < 2; ii++)
#pragma unroll
            for (int j = 0; j < 4; j++)
#pragma unroll
                for (int q = 0; q < 4; q++) acc[ii][j][q] = 0.f;

#pragma unroll
        for (int s = 0; s < 2; s++) {
            int q = lane >> 3, rr = lane & 7;
            int krow = s * 16 + (q & 1) * 8 + rr;
            uint32_t bH4[2][4], bL4[2][4];
#pragma unroll
            for (int j2 = 0; j2 < 2; j2++) {
                int ncol = nb * 64 + wn * 32 + (j2 * 2 + (q >> 1)) * 8;
                uint32_t off = (uint32_t)(krow * STRC) * 4u + (uint32_t)ncol * 2u;
                ldm_x4t(bH4[j2], sb + OFF_BHI + off);
                ldm_x4t(bL4[j2], sb + OFF_BLO + off);
            }
#pragma unroll
            for (int ii = 0; ii < 2; ii++)
#pragma unroll
                for (int j = 0; j < 4; j++) {
                    uint32_t bh0 = bH4[j >> 1][(j & 1) * 2];
                    uint32_t bh1 = bH4[j >> 1][(j & 1) * 2 + 1];
                    uint32_t bl0 = bL4[j >> 1][(j & 1) * 2];
                    uint32_t bl1 = bL4[j >> 1][(j & 1) * 2 + 1];
                    mma_bf16(acc[ii][j], aH[s][ii], bh0, bh1);
                    mma_bf16(acc[ii][j], aH[s][ii], bl0, bl1);
                    mma_bf16(acc[ii][j], aL[s][ii], bh0, bh1);
                }
        }

        // ---- epilogue: gather xl/xr, leaky, att-weighted partial sums
#pragma unroll
        for (int ii = 0; ii < 2; ii++) {
            int row1 = wm * 32 + ii * 16 + g;
            int row2 = row1 + 8;
            int s1 = ssrc[row1], d1 = sdst[row1];
            int s2 = ssrc[row2], d2 = sdst[row2];
#pragma unroll
            for (int j = 0; j < 4; j++) {
                int col = nb * 64 + wn * 32 + j * 8 + tg * 2;
                float2 av = *(float2*)&satt[col];
                float2 l1 = *(const float2*)&xl[(size_t)s1 * C + col];
                float2 q1 = *(const float2*)&xr[(size_t)d1 * C + col];
                float2 l2 = *(const float2*)&xl[(size_t)s2 * C + col];
                float2 q2 = *(const float2*)&xr[(size_t)d2 * C + col];
                float t0 = acc[ii][j][0] + l1.x + q1.x; t0 = t0 > 0.f ? t0 : 0.2f * t0;
                float t1 = acc[ii][j][1] + l1.y + q1.y; t1 = t1 > 0.f ? t1 : 0.2f * t1;
                float t2 = acc[ii][j][2] + l2.x + q2.x; t2 = t2 > 0.f ? t2 : 0.2f * t2;
                float t3 = acc[ii][j][3] + l2.y + q2.y; t3 = t3 > 0.f ? t3 : 0.2f * t3;
                sc[ii][0] += av.x * t0 + av.y * t1;
                sc[ii][1] += av.x * t2 + av.y * t3;
            }
        }
    }

    // ---- reduce across tg lanes, combine across wn warps via smem atomics
#pragma unroll
    for (int ii = 0; ii < 2; ii++)
#pragma unroll
        for (int h = 0; h < 2; h++) {
            float v = sc[ii][h];
            v += __shfl_xor_sync(0xffffffffu, v, 1);
            v += __shfl_xor_sync(0xffffffffu, v, 2);
            if (tg == 0) {
                int row = wm * 32 + ii * 16 + g + h * 8;
                atomicAdd(&sscore[row], v);
            }
        }
    __syncthreads();
    if (tid < 128 && r0 + tid < EE) g_escore[r0 + tid] = sscore[tid];
}

// ======================= self-loop score per node =========================
template <int C>
__global__ void k_eself(const float* __restrict__ We, const float* __restrict__ att,
                        const float* __restrict__ xl, const float* __restrict__ xr) {
    int gw = (blockIdx.x * blockDim.x + threadIdx.x) >> 5;
    int lane = threadIdx.x & 31;
    if (gw >= NN) return;
    float la = g_loopattr[(size_t)gw * ED + lane];
    float acc = 0.f;
#pragma unroll
    for (int jj = 0; jj < C / 32; jj++) {
        int j = jj * 32 + lane;
        float v = xl[(size_t)gw * C + j] + xr[(size_t)gw * C + j];
#pragma unroll
        for (int k = 0; k < ED; k++)
            v += __shfl_sync(0xffffffffu, la, k) * We[k * C + j];
        v = v > 0.f ? v : 0.2f * v;
        acc += att[j] * v;
    }
#pragma unroll
    for (int off = 16; off; off >>= 1) acc += __shfl_xor_sync(0xffffffffu, acc, off);
    if (lane == 0) g_eself[gw] = acc;
}

// ======================= softmax + aggregation (warp/node) ================
template <int C>
__global__ void k_aggregate(const int* __restrict__ esrc,
                            const float* __restrict__ xl,
                            const float* __restrict__ bias,
                            float* __restrict__ outp) {
    int gw = (blockIdx.x * blockDim.x + threadIdx.x) >> 5;
    int lane = threadIdx.x & 31;
    if (gw >= NN) return;
    int beg = g_ptr[gw], end = g_ptr[gw + 1];

    float m = g_eself[gw];
    for (int t = beg + lane; t < end; t += 32) m = fmaxf(m, g_escore[g_eid[t]]);
#pragma unroll
    for (int off = 16; off; off >>= 1) m = fmaxf(m, __shfl_xor_sync(0xffffffffu, m, off));

    float4 acc[C / 128];
#pragma unroll
    for (int jj = 0; jj < C / 128; jj++) acc[jj] = make_float4(0.f, 0.f, 0.f, 0.f);
    float denom = 0.f;

    for (int t = beg; t < end; t++) {
        int eid = g_eid[t];
        float w = expf(g_escore[eid] - m);
        int s = esrc[eid];
        denom += w;
#pragma unroll
        for (int jj = 0; jj < C / 128; jj++) {
            float4 x4 = *(const float4*)&xl[(size_t)s * C + jj * 128 + lane * 4];
            acc[jj].x += w * x4.x; acc[jj].y += w * x4.y;
            acc[jj].z += w * x4.z; acc[jj].w += w * x4.w;
        }
    }
    float ws = expf(g_eself[gw] - m);
    denom += ws;
#pragma unroll
    for (int jj = 0; jj < C / 128; jj++) {
        float4 x4 = *(const float4*)&xl[(size_t)gw * C + jj * 128 + lane * 4];
        acc[jj].x += ws * x4.x; acc[jj].y += ws * x4.y;
        acc[jj].z += ws * x4.z; acc[jj].w += ws * x4.w;
    }

    float inv = 1.f / denom;
#pragma unroll
    for (int jj = 0; jj < C / 128; jj++) {
        int c = jj * 128 + lane * 4;
        float4 b4 = *(const float4*)&bias[c];
        float4 o;
        o.x = fmaxf(acc[jj].x * inv + b4.x, 0.f);
        o.y = fmaxf(acc[jj].y * inv + b4.y, 0.f);
        o.z = fmaxf(acc[jj].z * inv + b4.z, 0.f);
        o.w = fmaxf(acc[jj].w * inv + b4.w, 0.f);
        *(float4*)&outp[(size_t)gw * C + c] = o;
    }
}

// ======================= global mean pool =================================
#define NPB 196
__global__ void k_pool2(const int* __restrict__ batch) {
    int tid = threadIdx.x;                 // 128 threads = H2 columns
    int n0 = blockIdx.x * NPB;
    int n1 = min(n0 + NPB, NN);
    if (n0 >= n1) return;
    int curg = batch[n0];
    float acc = 0.f;
    for (int n = n0; n < n1; n++) {
        int g = batch[n];
        if (g != curg) {
            atomicAdd(&g_pool[curg * H2 + tid], acc);
            acc = 0.f;
            curg = g;
        }
        acc += g_h2[(size_t)n * H2 + tid];
    }
    atomicAdd(&g_pool[curg * H2 + tid], acc);
}

// ======================= MLP head =========================================
__device__ __forceinline__ int lowerb(const int* b, int val) {
    int lo = 0, hi = NN;
    while (lo < hi) { int m = (lo + hi) >> 1; if (b[m] < val) lo = m + 1; else hi = m; }
    return lo;
}

__global__ void k_head(const int* __restrict__ batch,
                       const float* __restrict__ Wd1, const float* __restrict__ bd1,
                       const float* __restrict__ gma, const float* __restrict__ bta,
                       const float* __restrict__ mean, const float* __restrict__ var,
                       const float* __restrict__ Wd2, const float* __restrict__ bd2,
                       float* __restrict__ out) {
    __shared__ float sp[GG * H2];
    __shared__ float sh[GG * HD];
    __shared__ float scnt[GG];
    int tid = threadIdx.x;
    if (tid < GG)
        scnt[tid] = (float)(lowerb(batch, tid + 1) - lowerb(batch, tid));
    __syncthreads();
    for (int idx = tid; idx < GG * H2; idx += blockDim.x) {
        int g = idx / H2;
        sp[idx] = g_pool[idx] / fmaxf(scnt[g], 1.f);
    }
    __syncthreads();
    for (int idx = tid; idx < GG * HD; idx += blockDim.x) {
        int g = idx / HD, h = idx - g * HD;
        float a = bd1[h];
        for (int k = 0; k < H2; k++) a += sp[g * H2 + k] * Wd1[k * HD + h];
        a = (a - mean[h]) / sqrtf(var[h] + 1e-5f) * gma[h] + bta[h];
        a = a > 0.f ? a : 0.1f * a;
        sh[idx] = a;
    }
    __syncthreads();
    for (int idx = tid; idx < GG * OUTD; idx += blockDim.x) {
        int g = idx / OUTD, o = idx - g * OUTD;
        float a = bd2[o];
        for (int k = 0; k < HD; k++) a += sh[g * HD + k] * Wd2[k * OUTD + o];
        out[idx] = a;
    }
}

// ======================= launcher =========================================
extern "C" void kernel_launch(void* const* d_in, const int* in_sizes, int n_in,
                              void* d_out, int out_size) {
    const float* node_attr = (const float*)d_in[0];
    const float* edge_attr = (const float*)d_in[1];
    const int*   esrc      = (const int*)d_in[2];
    const int*   edst      = (const int*)d_in[3];
    const int*   batch     = (const int*)d_in[4];
    const float *Wl1 = (const float*)d_in[5],  *bl1 = (const float*)d_in[6];
    const float *Wr1 = (const float*)d_in[7],  *br1 = (const float*)d_in[8];
    const float *We1 = (const float*)d_in[9],  *att1 = (const float*)d_in[10], *b1 = (const float*)d_in[11];
    const float *Wl2 = (const float*)d_in[12], *bl2 = (const float*)d_in[13];
    const float *Wr2 = (const float*)d_in[14], *br2 = (const float*)d_in[15];
    const float *We2 = (const float*)d_in[16], *att2 = (const float*)d_in[17], *b2 = (const float*)d_in[18];
    const float *Wd1 = (const float*)d_in[19], *bd1 = (const float*)d_in[20];
    const float *gma = (const float*)d_in[21], *bta = (const float*)d_in[22];
    const float *mean = (const float*)d_in[23], *var = (const float*)d_in[24];
    const float *Wd2 = (const float*)d_in[25], *bd2 = (const float*)d_in[26];
    float* out = (float*)d_out;

    float *p_xl, *p_xr, *p_h1, *p_h2, *p_pool;
    int *p_deg, *p_cur;
    cudaGetSymbolAddress((void**)&p_xl, g_xl);
    cudaGetSymbolAddress((void**)&p_xr, g_xr);
    cudaGetSymbolAddress((void**)&p_h1, g_h1);
    cudaGetSymbolAddress((void**)&p_h2, g_h2);
    cudaGetSymbolAddress((void**)&p_pool, g_pool);
    cudaGetSymbolAddress((void**)&p_deg, g_deg);
    cudaGetSymbolAddress((void**)&p_cur, g_cur);

    // dynamic smem sizes for score kernels
    const int SC1 = 2 * 10240 + 2 * (32 * (H1 / 2 + 4) * 4) + 512 + 512 + H1 * 4 + 512;
    const int SC2 = 2 * 10240 + 2 * (32 * (H2 / 2 + 4) * 4) + 512 + 512 + H2 * 4 + 512;
    cudaFuncSetAttribute(k_score_mma<H1>, cudaFuncAttributeMaxDynamicSharedMemorySize, SC1);
    cudaFuncSetAttribute(k_score_mma<H2>, cudaFuncAttributeMaxDynamicSharedMemorySize, SC2);

    cudaMemsetAsync(p_deg, 0, NN * sizeof(int), 0);
    cudaMemsetAsync(p_cur, 0, NN * sizeof(int), 0);
    cudaMemsetAsync(p_pool, 0, GG * H2 * sizeof(float), 0);

    int nodeWB = (NN * 32 + 255) / 256;   // warp-per-node blocks
    int rowT = (NN + 127) / 128;          // 391
    int edgeT = (EE + 127) / 128;         // 3907

    // order arranged so k_score_mma<H1> is the 4th kernel launch (profiled)
    k_hist<<<(EE + 255) / 256, 256>>>(edst);
    k_scan_partial<<<NCHUNK, 1024>>>();
    k_mma_nodeZ<DIN><<<dim3(rowT, H1 / 64), 256>>>(
        node_attr, Wl1, bl1, p_xl, Wr1, br1, p_xr, NN, H1);
    k_score_mma<H1><<<edgeT, 256, SC1>>>(edge_attr, We1, esrc, edst, att1, p_xl, p_xr);
    k_scan_bsum<<<1, 64>>>();
    k_scan_final<<<NCHUNK, 1024>>>();
    k_scatter<<<(EE + 255) / 256, 256>>>(edst);
    k_loopmean<<<nodeWB, 256>>>(edge_attr);

    // ---------------- layer 1 remainder ----------------
    k_eself<H1><<<nodeWB, 256>>>(We1, att1, p_xl, p_xr);
    k_aggregate<H1><<<nodeWB, 256>>>(esrc, p_xl, b1, p_h1);

    // ---------------- layer 2 ----------------
    k_mma_nodeZ<H1><<<dim3(rowT, H2 / 64), 256>>>(
        p_h1, Wl2, bl2, p_xl, Wr2, br2, p_xr, NN, H2);
    k_score_mma<H2><<<edgeT, 256, SC2>>>(edge_attr, We2, esrc, edst, att2, p_xl, p_xr);
    k_eself<H2><<<nodeWB, 256>>>(We2, att2, p_xl, p_xr);
    k_aggregate<H2><<<nodeWB, 256>>>(esrc, p_xl, b2, p_h2);

    // ---------------- pool + head ----------------
    k_pool2<<<(NN + NPB - 1) / NPB, 128>>>(batch);
    k_head<<<1, 512>>>(batch, Wd1, bd1, gma, bta, mean, var, Wd2, bd2, out);
}

// round 9
// speedup vs baseline: 1.3480x; 1.1113x over previous
#include <cuda_runtime.h>
#include <cuda_bf16.h>
#include <math.h>
#include <stdint.h>

#define NN   50000
#define EE   500000
#define GG   64
#define DIN  128
#define ED   32
#define H1   256
#define H2   128
#define HD   64
#define OUTD 8
#define NCHUNK 49   // ceil(NN/1024)

// ---------------- scratch (device globals; no allocation allowed) ----------
__device__ float g_xl[(size_t)NN * H1];
__device__ float g_xr[(size_t)NN * H1];
__device__ float g_h1[(size_t)NN * H1];
__device__ float g_h2[(size_t)NN * H2];
__device__ float g_escore[EE];          // indexed by CSR position
__device__ float g_eself[NN];
__device__ float g_loopattr[(size_t)NN * ED];
__device__ int   g_deg[NN];
__device__ int   g_ptr[NN + 1];
__device__ int   g_cur[NN];
__device__ int   g_eid[EE];             // CSR pos -> original edge id
__device__ int   g_src_csr[EE];         // CSR pos -> src node
__device__ int   g_dst_csr[EE];         // CSR pos -> dst node
__device__ int   g_bsum[64];
__device__ float g_pool[GG * H2];

// ======================= helpers ==========================================
__device__ __forceinline__ uint32_t smem_u32(const void* p) {
    uint32_t a;
    asm("{ .reg .u64 t; cvta.to.shared.u64 t, %1; cvt.u32.u64 %0, t; }" : "=r"(a) : "l"(p));
    return a;
}
// pack two f32 (k-order: lo_k first) into bf16x2 word (low half = lo_k)
__device__ __forceinline__ uint32_t packbf(float lo_k, float hi_k) {
    uint32_t r;
    asm("cvt.rn.bf16x2.f32 %0, %1, %2;" : "=r"(r) : "f"(hi_k), "f"(lo_k));
    return r;
}
__device__ __forceinline__ void ldm_x4(uint32_t (&r)[4], uint32_t addr) {
    asm volatile("ldmatrix.sync.aligned.m8n8.x4.shared.b16 {%0,%1,%2,%3}, [%4];"
        : "=r"(r[0]), "=r"(r[1]), "=r"(r[2]), "=r"(r[3]) : "r"(addr));
}
__device__ __forceinline__ void ldm_x4t(uint32_t (&r)[4], uint32_t addr) {
    asm volatile("ldmatrix.sync.aligned.m8n8.x4.trans.shared.b16 {%0,%1,%2,%3}, [%4];"
        : "=r"(r[0]), "=r"(r[1]), "=r"(r[2]), "=r"(r[3]) : "r"(addr));
}
__device__ __forceinline__ void mma_bf16(float (&c)[4], const uint32_t (&a)[4],
                                         uint32_t b0, uint32_t b1) {
    asm volatile("mma.sync.aligned.m16n8k16.row.col.f32.bf16.bf16.f32 "
        "{%0,%1,%2,%3},{%4,%5,%6,%7},{%8,%9},{%0,%1,%2,%3};"
        : "+f"(c[0]), "+f"(c[1]), "+f"(c[2]), "+f"(c[3])
        : "r"(a[0]), "r"(a[1]), "r"(a[2]), "r"(a[3]), "r"(b0), "r"(b1));
}
// convert float4 -> hi/lo bf16x2 pair words
__device__ __forceinline__ void cvt4(const float4& v, uint32_t& h01, uint32_t& h23,
                                     uint32_t& l01, uint32_t& l23) {
    h01 = packbf(v.x, v.y);
    h23 = packbf(v.z, v.w);
    float r0 = v.x - __uint_as_float(h01 << 16);
    float r1 = v.y - __uint_as_float(h01 & 0xffff0000u);
    float r2 = v.z - __uint_as_float(h23 << 16);
    float r3 = v.w - __uint_as_float(h23 & 0xffff0000u);
    l01 = packbf(r0, r1);
    l23 = packbf(r2, r3);
}

// ======================= setup kernels ====================================
__global__ void k_hist(const int* __restrict__ edst) {
    int e = blockIdx.x * blockDim.x + threadIdx.x;
    if (e < EE) atomicAdd(&g_deg[edst[e]], 1);
}

__global__ void k_scan_partial() {
    __shared__ int sh[32];
    int tid = threadIdx.x;
    int i = blockIdx.x * 1024 + tid;
    int v = (i < NN) ? g_deg[i] : 0;
#pragma unroll
    for (int o = 16; o; o >>= 1) v += __shfl_xor_sync(0xffffffffu, v, o);
    if ((tid & 31) == 0) sh[tid >> 5] = v;
    __syncthreads();
    if (tid < 32) {
        int t = sh[tid];
#pragma unroll
        for (int o = 16; o; o >>= 1) t += __shfl_xor_sync(0xffffffffu, t, o);
        if (tid == 0) g_bsum[blockIdx.x] = t;
    }
}

__global__ void k_scan_bsum() {
    __shared__ int sh[64];
    int tid = threadIdx.x;
    int v = (tid < NCHUNK) ? g_bsum[tid] : 0;
    sh[tid] = v;
    __syncthreads();
    for (int off = 1; off < 64; off <<= 1) {
        int t = (tid >= off) ? sh[tid - off] : 0;
        __syncthreads();
        sh[tid] += t;
        __syncthreads();
    }
    if (tid < NCHUNK) g_bsum[tid] = sh[tid] - v;   // exclusive
    if (tid == 0) g_ptr[NN] = EE;
}

__global__ void k_scan_final() {
    __shared__ int sh[32];
    int tid = threadIdx.x, lane = tid & 31, wid = tid >> 5;
    int i = blockIdx.x * 1024 + tid;
    int v = (i < NN) ? g_deg[i] : 0;
    int incl = v;
#pragma unroll
    for (int o = 1; o < 32; o <<= 1) {
        int t = __shfl_up_sync(0xffffffffu, incl, o);
        if (lane >= o) incl += t;
    }
    if (lane == 31) sh[wid] = incl;
    __syncthreads();
    if (wid == 0) {
        int t = sh[lane];
#pragma unroll
        for (int o = 1; o < 32; o <<= 1) {
            int u = __shfl_up_sync(0xffffffffu, t, o);
            if (lane >= o) t += u;
        }
        sh[lane] = t;
    }
    __syncthreads();
    int base = g_bsum[blockIdx.x] + (wid ? sh[wid - 1] : 0);
    if (i < NN) g_ptr[i] = base + incl - v;
}

__global__ void k_scatter(const int* __restrict__ esrc, const int* __restrict__ edst) {
    int e = blockIdx.x * blockDim.x + threadIdx.x;
    if (e >= EE) return;
    int d = edst[e];
    int pos = g_ptr[d] + atomicAdd(&g_cur[d], 1);
    g_eid[pos] = e;
    g_src_csr[pos] = esrc[e];
    g_dst_csr[pos] = d;
}

__global__ void k_loopmean(const float* __restrict__ eattr) {
    int gw = (blockIdx.x * blockDim.x + threadIdx.x) >> 5;
    int lane = threadIdx.x & 31;
    if (gw >= NN) return;
    int beg = g_ptr[gw], end = g_ptr[gw + 1];
    float acc = 0.f;
    for (int t = beg; t < end; t++)
        acc += eattr[(size_t)g_eid[t] * ED + lane];
    g_loopattr[(size_t)gw * ED + lane] = acc / fmaxf((float)(end - beg), 1.f);
}

// ======================= mma.sync bf16x3 node GEMM (dual weight-set) ======
#define STRA 20   // A smem row stride in uint32 (40 bf16)
#define STRB 36   // B smem row stride in uint32 (72 bf16)

template <int KTOT>
__global__ void __launch_bounds__(256, 2)
k_mma_nodeZ(const float* __restrict__ A,
            const float* __restrict__ W0, const float* __restrict__ bias0, float* __restrict__ out0,
            const float* __restrict__ W1, const float* __restrict__ bias1, float* __restrict__ out1,
            int M, int Nc) {
    __shared__ __align__(16) uint32_t sAhi[128 * STRA];
    __shared__ __align__(16) uint32_t sAlo[128 * STRA];
    __shared__ __align__(16) uint32_t sBhi[2][32 * STRB];
    __shared__ __align__(16) uint32_t sBlo[2][32 * STRB];

    int tid = threadIdx.x, lane = tid & 31, w = tid >> 5;
    int wm = w & 3, wn = w >> 2;
    int row0 = blockIdx.x * 128, c0 = blockIdx.y * 64;

    uint32_t aHiB = smem_u32(sAhi), aLoB = smem_u32(sAlo);
    uint32_t bHiB0 = smem_u32(sBhi[0]), bLoB0 = smem_u32(sBlo[0]);

    float acc[2][2][4][4];   // [z][ii][j][q]
#pragma unroll
    for (int z = 0; z < 2; z++)
#pragma unroll
        for (int i = 0; i < 2; i++)
#pragma unroll
            for (int j = 0; j < 4; j++)
#pragma unroll
                for (int q = 0; q < 4; q++) acc[z][i][j][q] = 0.f;

    for (int k0 = 0; k0 < KTOT; k0 += 32) {
#pragma unroll
        for (int t = 0; t < 4; t++) {
            int idx = tid + t * 256;
            int r = idx >> 3, c4 = (idx & 7) * 4;
            float4 v = make_float4(0.f, 0.f, 0.f, 0.f);
            if (row0 + r < M)
                v = *(const float4*)&A[(size_t)(row0 + r) * KTOT + k0 + c4];
            uint32_t h01, h23, l01, l23;
            cvt4(v, h01, h23, l01, l23);
            int o = r * STRA + (c4 >> 1);
            sAhi[o] = h01; sAhi[o + 1] = h23;
            sAlo[o] = l01; sAlo[o + 1] = l23;
        }
#pragma unroll
        for (int t = 0; t < 4; t++) {
            int idx = tid + t * 256;           // 0..1023
            int z = idx >> 9;                  // 512 per z
            int rem = idx & 511;
            int r = rem >> 4, c4 = (rem & 15) * 4;
            const float* Wz = z ? W1 : W0;
            float4 v = *(const float4*)&Wz[(size_t)(k0 + r) * Nc + c0 + c4];
            uint32_t h01, h23, l01, l23;
            cvt4(v, h01, h23, l01, l23);
            int o = r * STRB + (c4 >> 1);
            sBhi[z][o] = h01; sBhi[z][o + 1] = h23;
            sBlo[z][o] = l01; sBlo[z][o + 1] = l23;
        }
        __syncthreads();

#pragma unroll
        for (int s = 0; s < 2; s++) {
            uint32_t aH[2][4], aL[2][4];
#pragma unroll
            for (int ii = 0; ii < 2; ii++) {
                int tile = lane >> 3, rr = lane & 7;
                int row = wm * 32 + ii * 16 + (tile & 1) * 8 + rr;
                int kk = s * 16 + (tile >> 1) * 8;
                uint32_t off = (uint32_t)(row * STRA) * 4u + (uint32_t)kk * 2u;
                ldm_x4(aH[ii], aHiB + off);
                ldm_x4(aL[ii], aLoB + off);
            }
            int q = lane >> 3, rr = lane & 7;
            int krow = s * 16 + (q & 1) * 8 + rr;
#pragma unroll
            for (int z = 0; z < 2; z++) {
                uint32_t zb = (uint32_t)(z * 32 * STRB * 4);
                uint32_t bH4[2][4], bL4[2][4];
#pragma unroll
                for (int j2 = 0; j2 < 2; j2++) {
                    int ncol = wn * 32 + (j2 * 2 + (q >> 1)) * 8;
                    uint32_t off = (uint32_t)(krow * STRB) * 4u + (uint32_t)ncol * 2u;
                    ldm_x4t(bH4[j2], bHiB0 + zb + off);
                    ldm_x4t(bL4[j2], bLoB0 + zb + off);
                }
#pragma unroll
                for (int ii = 0; ii < 2; ii++)
#pragma unroll
                    for (int j = 0; j < 4; j++) {
                        uint32_t bh0 = bH4[j >> 1][(j & 1) * 2];
                        uint32_t bh1 = bH4[j >> 1][(j & 1) * 2 + 1];
                        uint32_t bl0 = bL4[j >> 1][(j & 1) * 2];
                        uint32_t bl1 = bL4[j >> 1][(j & 1) * 2 + 1];
                        mma_bf16(acc[z][ii][j], aH[ii], bh0, bh1);
                        mma_bf16(acc[z][ii][j], aH[ii], bl0, bl1);
                        mma_bf16(acc[z][ii][j], aL[ii], bh0, bh1);
                    }
            }
        }
        __syncthreads();
    }

    int g = lane >> 2, tg = lane & 3;
#pragma unroll
    for (int z = 0; z < 2; z++) {
        const float* bias = z ? bias1 : bias0;
        float* out        = z ? out1 : out0;
#pragma unroll
        for (int i = 0; i < 2; i++) {
            int r1 = row0 + wm * 32 + i * 16 + g;
            int r2 = r1 + 8;
#pragma unroll
            for (int j = 0; j < 4; j++) {
                int col = c0 + wn * 32 + j * 8 + tg * 2;
                float2 bv = *(const float2*)&bias[col];
                if (r1 < M) {
                    float2 o = make_float2(acc[z][i][j][0] + bv.x, acc[z][i][j][1] + bv.y);
                    *(float2*)&out[(size_t)r1 * Nc + col] = o;
                }
                if (r2 < M) {
                    float2 o = make_float2(acc[z][i][j][2] + bv.x, acc[z][i][j][3] + bv.y);
                    *(float2*)&out[(size_t)r2 * Nc + col] = o;
                }
            }
        }
    }
}

// ======================= tensorized edge-score kernel (CSR order) =========
// CTA = 128 CSR slots x ALL C cols. eattr rows fetched via g_eid (full-line
// gathers); src/dst contiguous from CSR arrays; dst-sorted order gives xr
// gather locality. Scores written at CSR positions. No global atomics.
template <int C>
__global__ void __launch_bounds__(256, 2)
k_score_mma(const float* __restrict__ eattr, const float* __restrict__ We,
            const float* __restrict__ att,
            const float* __restrict__ xl, const float* __restrict__ xr) {
    constexpr int STRC = C / 2 + 4;            // We smem row stride (u32)
    constexpr int ASZ = 128 * STRA * 4;        // 10240
    constexpr int BSZ = 32 * STRC * 4;
    constexpr int OFF_ALO = ASZ;
    constexpr int OFF_BHI = 2 * ASZ;
    constexpr int OFF_BLO = 2 * ASZ + BSZ;
    constexpr int OFF_SRC = 2 * ASZ + 2 * BSZ;
    constexpr int OFF_DST = OFF_SRC + 512;
    constexpr int OFF_ATT = OFF_DST + 512;
    constexpr int OFF_SC  = OFF_ATT + C * 4;

    extern __shared__ char smem[];
    uint32_t sb = smem_u32(smem);
    uint32_t* sAhi = (uint32_t*)smem;
    uint32_t* sAlo = (uint32_t*)(smem + OFF_ALO);
    uint32_t* sBhi = (uint32_t*)(smem + OFF_BHI);
    uint32_t* sBlo = (uint32_t*)(smem + OFF_BLO);
    int* ssrc   = (int*)(smem + OFF_SRC);
    int* sdst   = (int*)(smem + OFF_DST);
    float* satt = (float*)(smem + OFF_ATT);
    float* sscore = (float*)(smem + OFF_SC);

    int tid = threadIdx.x, lane = tid & 31, w = tid >> 5;
    int wm = w & 3, wn = w >> 2;
    int r0 = blockIdx.x * 128;

    // ---- A: eattr rows (via CSR eid) 128x32 -> hi/lo bf16
#pragma unroll
    for (int t = 0; t < 4; t++) {
        int idx = tid + t * 256;
        int r = idx >> 3, c4 = (idx & 7) * 4;
        float4 v = make_float4(0.f, 0.f, 0.f, 0.f);
        if (r0 + r < EE) {
            int e = g_eid[r0 + r];
            v = *(const float4*)&eattr[(size_t)e * ED + c4];
        }
        uint32_t h01, h23, l01, l23;
        cvt4(v, h01, h23, l01, l23);
        int o = r * STRA + (c4 >> 1);
        sAhi[o] = h01; sAhi[o + 1] = h23;
        sAlo[o] = l01; sAlo[o + 1] = l23;
    }
    // ---- B: We 32xC -> hi/lo bf16
    for (int idx = tid; idx < 32 * (C / 4); idx += 256) {
        int r = idx / (C / 4), c4 = (idx % (C / 4)) * 4;
        float4 v = *(const float4*)&We[(size_t)r * C + c4];
        uint32_t h01, h23, l01, l23;
        cvt4(v, h01, h23, l01, l23);
        int o = r * STRC + (c4 >> 1);
        sBhi[o] = h01; sBhi[o + 1] = h23;
        sBlo[o] = l01; sBlo[o + 1] = l23;
    }
    if (tid < 128) {
        int t = r0 + tid;
        ssrc[tid] = (t < EE) ? g_src_csr[t] : 0;
        sdst[tid] = (t < EE) ? g_dst_csr[t] : 0;
        sscore[tid] = 0.f;
    }
    for (int c = tid; c < C; c += 256) satt[c] = att[c];
    __syncthreads();

    // ---- A fragments (K=32 fixed, loaded once)
    uint32_t aH[2][2][4], aL[2][2][4];   // [s][ii]
#pragma unroll
    for (int s = 0; s < 2; s++)
#pragma unroll
        for (int ii = 0; ii < 2; ii++) {
            int tile = lane >> 3, rr = lane & 7;
            int row = wm * 32 + ii * 16 + (tile & 1) * 8 + rr;
            int kk = s * 16 + (tile >> 1) * 8;
            uint32_t off = (uint32_t)(row * STRA) * 4u + (uint32_t)kk * 2u;
            ldm_x4(aH[s][ii], sb + off);
            ldm_x4(aL[s][ii], sb + OFF_ALO + off);
        }

    int g = lane >> 2, tg = lane & 3;
    float sc[2][2] = {{0.f, 0.f}, {0.f, 0.f}};   // [ii][rowhalf]

#pragma unroll
    for (int nb = 0; nb < C / 64; nb++) {
        float acc[2][4][4];
#pragma unroll
        for (int ii = 0; ii < 2; ii++)
#pragma unroll
            for (int j = 0; j < 4; j++)
#pragma unroll
                for (int q = 0; q < 4; q++) acc[ii][j][q] = 0.f;

#pragma unroll
        for (int s = 0; s < 2; s++) {
            int q = lane >> 3, rr = lane & 7;
            int krow = s * 16 + (q & 1) * 8 + rr;
            uint32_t bH4[2][4], bL4[2][4];
#pragma unroll
            for (int j2 = 0; j2 < 2; j2++) {
                int ncol = nb * 64 + wn * 32 + (j2 * 2 + (q >> 1)) * 8;
                uint32_t off = (uint32_t)(krow * STRC) * 4u + (uint32_t)ncol * 2u;
                ldm_x4t(bH4[j2], sb + OFF_BHI + off);
                ldm_x4t(bL4[j2], sb + OFF_BLO + off);
            }
#pragma unroll
            for (int ii = 0; ii < 2; ii++)
#pragma unroll
                for (int j = 0; j < 4; j++) {
                    uint32_t bh0 = bH4[j >> 1][(j & 1) * 2];
                    uint32_t bh1 = bH4[j >> 1][(j & 1) * 2 + 1];
                    uint32_t bl0 = bL4[j >> 1][(j & 1) * 2];
                    uint32_t bl1 = bL4[j >> 1][(j & 1) * 2 + 1];
                    mma_bf16(acc[ii][j], aH[s][ii], bh0, bh1);
                    mma_bf16(acc[ii][j], aH[s][ii], bl0, bl1);
                    mma_bf16(acc[ii][j], aL[s][ii], bh0, bh1);
                }
        }

        // ---- epilogue: gather xl/xr (xr has dst-run locality), leaky, att
#pragma unroll
        for (int ii = 0; ii < 2; ii++) {
            int row1 = wm * 32 + ii * 16 + g;
            int row2 = row1 + 8;
            int s1 = ssrc[row1], d1 = sdst[row1];
            int s2 = ssrc[row2], d2 = sdst[row2];
#pragma unroll
            for (int j = 0; j < 4; j++) {
                int col = nb * 64 + wn * 32 + j * 8 + tg * 2;
                float2 av = *(float2*)&satt[col];
                float2 l1 = *(const float2*)&xl[(size_t)s1 * C + col];
                float2 q1 = *(const float2*)&xr[(size_t)d1 * C + col];
                float2 l2 = *(const float2*)&xl[(size_t)s2 * C + col];
                float2 q2 = *(const float2*)&xr[(size_t)d2 * C + col];
                float t0 = acc[ii][j][0] + l1.x + q1.x; t0 = t0 > 0.f ? t0 : 0.2f * t0;
                float t1 = acc[ii][j][1] + l1.y + q1.y; t1 = t1 > 0.f ? t1 : 0.2f * t1;
                float t2 = acc[ii][j][2] + l2.x + q2.x; t2 = t2 > 0.f ? t2 : 0.2f * t2;
                float t3 = acc[ii][j][3] + l2.y + q2.y; t3 = t3 > 0.f ? t3 : 0.2f * t3;
                sc[ii][0] += av.x * t0 + av.y * t1;
                sc[ii][1] += av.x * t2 + av.y * t3;
            }
        }
    }

    // ---- reduce across tg lanes, combine across wn warps via smem atomics
#pragma unroll
    for (int ii = 0; ii < 2; ii++)
#pragma unroll
        for (int h = 0; h < 2; h++) {
            float v = sc[ii][h];
            v += __shfl_xor_sync(0xffffffffu, v, 1);
            v += __shfl_xor_sync(0xffffffffu, v, 2);
            if (tg == 0) {
                int row = wm * 32 + ii * 16 + g + h * 8;
                atomicAdd(&sscore[row], v);
            }
        }
    __syncthreads();
    if (tid < 128 && r0 + tid < EE) g_escore[r0 + tid] = sscore[tid];
}

// ======================= self-loop score per node =========================
template <int C>
__global__ void k_eself(const float* __restrict__ We, const float* __restrict__ att,
                        const float* __restrict__ xl, const float* __restrict__ xr) {
    int gw = (blockIdx.x * blockDim.x + threadIdx.x) >> 5;
    int lane = threadIdx.x & 31;
    if (gw >= NN) return;
    float la = g_loopattr[(size_t)gw * ED + lane];
    float acc = 0.f;
#pragma unroll
    for (int jj = 0; jj < C / 32; jj++) {
        int j = jj * 32 + lane;
        float v = xl[(size_t)gw * C + j] + xr[(size_t)gw * C + j];
#pragma unroll
        for (int k = 0; k < ED; k++)
            v += __shfl_sync(0xffffffffu, la, k) * We[k * C + j];
        v = v > 0.f ? v : 0.2f * v;
        acc += att[j] * v;
    }
#pragma unroll
    for (int off = 16; off; off >>= 1) acc += __shfl_xor_sync(0xffffffffu, acc, off);
    if (lane == 0) g_eself[gw] = acc;
}

// ======================= softmax + aggregation (warp/node, CSR) ===========
template <int C>
__global__ void k_aggregate(const float* __restrict__ bias,
                            const float* __restrict__ xl,
                            float* __restrict__ outp) {
    int gw = (blockIdx.x * blockDim.x + threadIdx.x) >> 5;
    int lane = threadIdx.x & 31;
    if (gw >= NN) return;
    int beg = g_ptr[gw], end = g_ptr[gw + 1];

    float m = g_eself[gw];
    for (int t = beg + lane; t < end; t += 32) m = fmaxf(m, g_escore[t]);
#pragma unroll
    for (int off = 16; off; off >>= 1) m = fmaxf(m, __shfl_xor_sync(0xffffffffu, m, off));

    float4 acc[C / 128];
#pragma unroll
    for (int jj = 0; jj < C / 128; jj++) acc[jj] = make_float4(0.f, 0.f, 0.f, 0.f);
    float denom = 0.f;

    for (int t = beg; t < end; t++) {
        float w = expf(g_escore[t] - m);
        int s = g_src_csr[t];
        denom += w;
#pragma unroll
        for (int jj = 0; jj < C / 128; jj++) {
            float4 x4 = *(const float4*)&xl[(size_t)s * C + jj * 128 + lane * 4];
            acc[jj].x += w * x4.x; acc[jj].y += w * x4.y;
            acc[jj].z += w * x4.z; acc[jj].w += w * x4.w;
        }
    }
    float ws = expf(g_eself[gw] - m);
    denom += ws;
#pragma unroll
    for (int jj = 0; jj < C / 128; jj++) {
        float4 x4 = *(const float4*)&xl[(size_t)gw * C + jj * 128 + lane * 4];
        acc[jj].x += ws * x4.x; acc[jj].y += ws * x4.y;
        acc[jj].z += ws * x4.z; acc[jj].w += ws * x4.w;
    }

    float inv = 1.f / denom;
#pragma unroll
    for (int jj = 0; jj < C / 128; jj++) {
        int c = jj * 128 + lane * 4;
        float4 b4 = *(const float4*)&bias[c];
        float4 o;
        o.x = fmaxf(acc[jj].x * inv + b4.x, 0.f);
        o.y = fmaxf(acc[jj].y * inv + b4.y, 0.f);
        o.z = fmaxf(acc[jj].z * inv + b4.z, 0.f);
        o.w = fmaxf(acc[jj].w * inv + b4.w, 0.f);
        *(float4*)&outp[(size_t)gw * C + c] = o;
    }
}

// ======================= global mean pool =================================
#define NPB 196
__global__ void k_pool2(const int* __restrict__ batch) {
    int tid = threadIdx.x;                 // 128 threads = H2 columns
    int n0 = blockIdx.x * NPB;
    int n1 = min(n0 + NPB, NN);
    if (n0 >= n1) return;
    int curg = batch[n0];
    float acc = 0.f;
    for (int n = n0; n < n1; n++) {
        int g = batch[n];
        if (g != curg) {
            atomicAdd(&g_pool[curg * H2 + tid], acc);
            acc = 0.f;
            curg = g;
        }
        acc += g_h2[(size_t)n * H2 + tid];
    }
    atomicAdd(&g_pool[curg * H2 + tid], acc);
}

// ======================= MLP head =========================================
__device__ __forceinline__ int lowerb(const int* b, int val) {
    int lo = 0, hi = NN;
    while (lo < hi) { int m = (lo + hi) >> 1; if (b[m] < val) lo = m + 1; else hi = m; }
    return lo;
}

__global__ void k_head(const int* __restrict__ batch,
                       const float* __restrict__ Wd1, const float* __restrict__ bd1,
                       const float* __restrict__ gma, const float* __restrict__ bta,
                       const float* __restrict__ mean, const float* __restrict__ var,
                       const float* __restrict__ Wd2, const float* __restrict__ bd2,
                       float* __restrict__ out) {
    __shared__ float sp[GG * H2];
    __shared__ float sh[GG * HD];
    __shared__ float scnt[GG];
    int tid = threadIdx.x;
    if (tid < GG)
        scnt[tid] = (float)(lowerb(batch, tid + 1) - lowerb(batch, tid));
    __syncthreads();
    for (int idx = tid; idx < GG * H2; idx += blockDim.x) {
        int g = idx / H2;
        sp[idx] = g_pool[idx] / fmaxf(scnt[g], 1.f);
    }
    __syncthreads();
    for (int idx = tid; idx < GG * HD; idx += blockDim.x) {
        int g = idx / HD, h = idx - g * HD;
        float a = bd1[h];
        for (int k = 0; k < H2; k++) a += sp[g * H2 + k] * Wd1[k * HD + h];
        a = (a - mean[h]) / sqrtf(var[h] + 1e-5f) * gma[h] + bta[h];
        a = a > 0.f ? a : 0.1f * a;
        sh[idx] = a;
    }
    __syncthreads();
    for (int idx = tid; idx < GG * OUTD; idx += blockDim.x) {
        int g = idx / OUTD, o = idx - g * OUTD;
        float a = bd2[o];
        for (int k = 0; k < HD; k++) a += sh[g * HD + k] * Wd2[k * OUTD + o];
        out[idx] = a;
    }
}

// ======================= launcher =========================================
extern "C" void kernel_launch(void* const* d_in, const int* in_sizes, int n_in,
                              void* d_out, int out_size) {
    const float* node_attr = (const float*)d_in[0];
    const float* edge_attr = (const float*)d_in[1];
    const int*   esrc      = (const int*)d_in[2];
    const int*   edst      = (const int*)d_in[3];
    const int*   batch     = (const int*)d_in[4];
    const float *Wl1 = (const float*)d_in[5],  *bl1 = (const float*)d_in[6];
    const float *Wr1 = (const float*)d_in[7],  *br1 = (const float*)d_in[8];
    const float *We1 = (const float*)d_in[9],  *att1 = (const float*)d_in[10], *b1 = (const float*)d_in[11];
    const float *Wl2 = (const float*)d_in[12], *bl2 = (const float*)d_in[13];
    const float *Wr2 = (const float*)d_in[14], *br2 = (const float*)d_in[15];
    const float *We2 = (const float*)d_in[16], *att2 = (const float*)d_in[17], *b2 = (const float*)d_in[18];
    const float *Wd1 = (const float*)d_in[19], *bd1 = (const float*)d_in[20];
    const float *gma = (const float*)d_in[21], *bta = (const float*)d_in[22];
    const float *mean = (const float*)d_in[23], *var = (const float*)d_in[24];
    const float *Wd2 = (const float*)d_in[25], *bd2 = (const float*)d_in[26];
    float* out = (float*)d_out;

    float *p_xl, *p_xr, *p_h1, *p_h2, *p_pool;
    int *p_deg, *p_cur;
    cudaGetSymbolAddress((void**)&p_xl, g_xl);
    cudaGetSymbolAddress((void**)&p_xr, g_xr);
    cudaGetSymbolAddress((void**)&p_h1, g_h1);
    cudaGetSymbolAddress((void**)&p_h2, g_h2);
    cudaGetSymbolAddress((void**)&p_pool, g_pool);
    cudaGetSymbolAddress((void**)&p_deg, g_deg);
    cudaGetSymbolAddress((void**)&p_cur, g_cur);

    // dynamic smem sizes for score kernels
    const int SC1 = 2 * 10240 + 2 * (32 * (H1 / 2 + 4) * 4) + 512 + 512 + H1 * 4 + 512;
    const int SC2 = 2 * 10240 + 2 * (32 * (H2 / 2 + 4) * 4) + 512 + 512 + H2 * 4 + 512;
    cudaFuncSetAttribute(k_score_mma<H1>, cudaFuncAttributeMaxDynamicSharedMemorySize, SC1);
    cudaFuncSetAttribute(k_score_mma<H2>, cudaFuncAttributeMaxDynamicSharedMemorySize, SC2);

    cudaMemsetAsync(p_deg, 0, NN * sizeof(int), 0);
    cudaMemsetAsync(p_cur, 0, NN * sizeof(int), 0);
    cudaMemsetAsync(p_pool, 0, GG * H2 * sizeof(float), 0);

    int nodeWB = (NN * 32 + 255) / 256;   // warp-per-node blocks
    int rowT = (NN + 127) / 128;          // 391
    int edgeT = (EE + 127) / 128;         // 3907

    // k_mma_nodeZ<DIN> sits in the profiler's capture slot (control)
    k_hist<<<(EE + 255) / 256, 256>>>(edst);
    k_scan_partial<<<NCHUNK, 1024>>>();
    k_scan_bsum<<<1, 64>>>();
    k_mma_nodeZ<DIN><<<dim3(rowT, H1 / 64), 256>>>(
        node_attr, Wl1, bl1, p_xl, Wr1, br1, p_xr, NN, H1);
    k_scan_final<<<NCHUNK, 1024>>>();
    k_scatter<<<(EE + 255) / 256, 256>>>(esrc, edst);
    k_loopmean<<<nodeWB, 256>>>(edge_attr);

    // ---------------- layer 1 ----------------
    k_score_mma<H1><<<edgeT, 256, SC1>>>(edge_attr, We1, att1, p_xl, p_xr);
    k_eself<H1><<<nodeWB, 256>>>(We1, att1, p_xl, p_xr);
    k_aggregate<H1><<<nodeWB, 256>>>(b1, p_xl, p_h1);

    // ---------------- layer 2 ----------------
    k_mma_nodeZ<H1><<<dim3(rowT, H2 / 64), 256>>>(
        p_h1, Wl2, bl2, p_xl, Wr2, br2, p_xr, NN, H2);
    k_score_mma<H2><<<edgeT, 256, SC2>>>(edge_attr, We2, att2, p_xl, p_xr);
    k_eself<H2><<<nodeWB, 256>>>(We2, att2, p_xl, p_xr);
    k_aggregate<H2><<<nodeWB, 256>>>(b2, p_xl, p_h2);

    // ---------------- pool + head ----------------
    k_pool2<<<(NN + NPB - 1) / NPB, 128>>>(batch);
    k_head<<<1, 512>>>(batch, Wd1, bd1, gma, bta, mean, var, Wd2, bd2, out);
}

// round 10
// speedup vs baseline: 1.3602x; 1.0091x over previous
#include <cuda_runtime.h>
#include <cuda_bf16.h>
#include <math.h>
#include <stdint.h>

#define NN   50000
#define EE   500000
#define GG   64
#define DIN  128
#define ED   32
#define H1   256
#define H2   128
#define HD   64
#define OUTD 8
#define NCHUNK 49   // ceil(NN/1024)

// ---------------- scratch (device globals; no allocation allowed) ----------
__device__ float g_xl[(size_t)NN * H1];
__device__ float g_xr[(size_t)NN * H1];
__device__ float g_h1[(size_t)NN * H1];
__device__ float g_h2[(size_t)NN * H2];
__device__ float g_escore[EE];          // indexed by CSR position
__device__ float g_eself[NN];
__device__ float g_loopattr[(size_t)NN * ED];
__device__ int   g_deg[NN];
__device__ int   g_ptr[NN + 1];
__device__ int   g_cur[NN];
__device__ int   g_eid[EE];             // CSR pos -> original edge id
__device__ int   g_src_csr[EE];         // CSR pos -> src node
__device__ int   g_dst_csr[EE];         // CSR pos -> dst node
__device__ int   g_bsum[64];
__device__ float g_pool[GG * H2];

// ======================= helpers ==========================================
__device__ __forceinline__ uint32_t smem_u32(const void* p) {
    uint32_t a;
    asm("{ .reg .u64 t; cvta.to.shared.u64 t, %1; cvt.u32.u64 %0, t; }" : "=r"(a) : "l"(p));
    return a;
}
// pack two f32 (k-order: lo_k first) into bf16x2 word (low half = lo_k)
__device__ __forceinline__ uint32_t packbf(float lo_k, float hi_k) {
    uint32_t r;
    asm("cvt.rn.bf16x2.f32 %0, %1, %2;" : "=r"(r) : "f"(hi_k), "f"(lo_k));
    return r;
}
__device__ __forceinline__ void ldm_x4(uint32_t (&r)[4], uint32_t addr) {
    asm volatile("ldmatrix.sync.aligned.m8n8.x4.shared.b16 {%0,%1,%2,%3}, [%4];"
        : "=r"(r[0]), "=r"(r[1]), "=r"(r[2]), "=r"(r[3]) : "r"(addr));
}
__device__ __forceinline__ void ldm_x4t(uint32_t (&r)[4], uint32_t addr) {
    asm volatile("ldmatrix.sync.aligned.m8n8.x4.trans.shared.b16 {%0,%1,%2,%3}, [%4];"
        : "=r"(r[0]), "=r"(r[1]), "=r"(r[2]), "=r"(r[3]) : "r"(addr));
}
__device__ __forceinline__ void mma_bf16(float (&c)[4], const uint32_t (&a)[4],
                                         uint32_t b0, uint32_t b1) {
    asm volatile("mma.sync.aligned.m16n8k16.row.col.f32.bf16.bf16.f32 "
        "{%0,%1,%2,%3},{%4,%5,%6,%7},{%8,%9},{%0,%1,%2,%3};"
        : "+f"(c[0]), "+f"(c[1]), "+f"(c[2]), "+f"(c[3])
        : "r"(a[0]), "r"(a[1]), "r"(a[2]), "r"(a[3]), "r"(b0), "r"(b1));
}
// convert float4 -> hi/lo bf16x2 pair words
__device__ __forceinline__ void cvt4(const float4& v, uint32_t& h01, uint32_t& h23,
                                     uint32_t& l01, uint32_t& l23) {
    h01 = packbf(v.x, v.y);
    h23 = packbf(v.z, v.w);
    float r0 = v.x - __uint_as_float(h01 << 16);
    float r1 = v.y - __uint_as_float(h01 & 0xffff0000u);
    float r2 = v.z - __uint_as_float(h23 << 16);
    float r3 = v.w - __uint_as_float(h23 & 0xffff0000u);
    l01 = packbf(r0, r1);
    l23 = packbf(r2, r3);
}

// ======================= setup kernels ====================================
__global__ void k_hist(const int* __restrict__ edst) {
    int e = blockIdx.x * blockDim.x + threadIdx.x;
    if (e < EE) atomicAdd(&g_deg[edst[e]], 1);
}

__global__ void k_scan_partial() {
    __shared__ int sh[32];
    int tid = threadIdx.x;
    int i = blockIdx.x * 1024 + tid;
    int v = (i < NN) ? g_deg[i] : 0;
#pragma unroll
    for (int o = 16; o; o >>= 1) v += __shfl_xor_sync(0xffffffffu, v, o);
    if ((tid & 31) == 0) sh[tid >> 5] = v;
    __syncthreads();
    if (tid < 32) {
        int t = sh[tid];
#pragma unroll
        for (int o = 16; o; o >>= 1) t += __shfl_xor_sync(0xffffffffu, t, o);
        if (tid == 0) g_bsum[blockIdx.x] = t;
    }
}

__global__ void k_scan_bsum() {
    __shared__ int sh[64];
    int tid = threadIdx.x;
    int v = (tid < NCHUNK) ? g_bsum[tid] : 0;
    sh[tid] = v;
    __syncthreads();
    for (int off = 1; off < 64; off <<= 1) {
        int t = (tid >= off) ? sh[tid - off] : 0;
        __syncthreads();
        sh[tid] += t;
        __syncthreads();
    }
    if (tid < NCHUNK) g_bsum[tid] = sh[tid] - v;   // exclusive
    if (tid == 0) g_ptr[NN] = EE;
}

__global__ void k_scan_final() {
    __shared__ int sh[32];
    int tid = threadIdx.x, lane = tid & 31, wid = tid >> 5;
    int i = blockIdx.x * 1024 + tid;
    int v = (i < NN) ? g_deg[i] : 0;
    int incl = v;
#pragma unroll
    for (int o = 1; o < 32; o <<= 1) {
        int t = __shfl_up_sync(0xffffffffu, incl, o);
        if (lane >= o) incl += t;
    }
    if (lane == 31) sh[wid] = incl;
    __syncthreads();
    if (wid == 0) {
        int t = sh[lane];
#pragma unroll
        for (int o = 1; o < 32; o <<= 1) {
            int u = __shfl_up_sync(0xffffffffu, t, o);
            if (lane >= o) t += u;
        }
        sh[lane] = t;
    }
    __syncthreads();
    int base = g_bsum[blockIdx.x] + (wid ? sh[wid - 1] : 0);
    if (i < NN) g_ptr[i] = base + incl - v;
}

__global__ void k_scatter(const int* __restrict__ esrc, const int* __restrict__ edst) {
    int e = blockIdx.x * blockDim.x + threadIdx.x;
    if (e >= EE) return;
    int d = edst[e];
    int pos = g_ptr[d] + atomicAdd(&g_cur[d], 1);
    g_eid[pos] = e;
    g_src_csr[pos] = esrc[e];
    g_dst_csr[pos] = d;
}

__global__ void k_loopmean(const float* __restrict__ eattr) {
    int gw = (blockIdx.x * blockDim.x + threadIdx.x) >> 5;
    int lane = threadIdx.x & 31;
    if (gw >= NN) return;
    int beg = g_ptr[gw], end = g_ptr[gw + 1];
    float acc = 0.f;
    for (int t = beg; t < end; t++)
        acc += eattr[(size_t)g_eid[t] * ED + lane];
    g_loopattr[(size_t)gw * ED + lane] = acc / fmaxf((float)(end - beg), 1.f);
}

// ======================= mma.sync bf16x3 node GEMM (dual weight-set) ======
#define STRA 20   // A smem row stride in uint32 (40 bf16)
#define STRB 36   // B smem row stride in uint32 (72 bf16)

template <int KTOT>
__global__ void __launch_bounds__(256, 2)
k_mma_nodeZ(const float* __restrict__ A,
            const float* __restrict__ W0, const float* __restrict__ bias0, float* __restrict__ out0,
            const float* __restrict__ W1, const float* __restrict__ bias1, float* __restrict__ out1,
            int M, int Nc) {
    __shared__ __align__(16) uint32_t sAhi[128 * STRA];
    __shared__ __align__(16) uint32_t sAlo[128 * STRA];
    __shared__ __align__(16) uint32_t sBhi[2][32 * STRB];
    __shared__ __align__(16) uint32_t sBlo[2][32 * STRB];

    int tid = threadIdx.x, lane = tid & 31, w = tid >> 5;
    int wm = w & 3, wn = w >> 2;
    int row0 = blockIdx.x * 128, c0 = blockIdx.y * 64;

    uint32_t aHiB = smem_u32(sAhi), aLoB = smem_u32(sAlo);
    uint32_t bHiB0 = smem_u32(sBhi[0]), bLoB0 = smem_u32(sBlo[0]);

    float acc[2][2][4][4];   // [z][ii][j][q]
#pragma unroll
    for (int z = 0; z < 2; z++)
#pragma unroll
        for (int i = 0; i < 2; i++)
#pragma unroll
            for (int j = 0; j < 4; j++)
#pragma unroll
                for (int q = 0; q < 4; q++) acc[z][i][j][q] = 0.f;

    for (int k0 = 0; k0 < KTOT; k0 += 32) {
#pragma unroll
        for (int t = 0; t < 4; t++) {
            int idx = tid + t * 256;
            int r = idx >> 3, c4 = (idx & 7) * 4;
            float4 v = make_float4(0.f, 0.f, 0.f, 0.f);
            if (row0 + r < M)
                v = *(const float4*)&A[(size_t)(row0 + r) * KTOT + k0 + c4];
            uint32_t h01, h23, l01, l23;
            cvt4(v, h01, h23, l01, l23);
            int o = r * STRA + (c4 >> 1);
            sAhi[o] = h01; sAhi[o + 1] = h23;
            sAlo[o] = l01; sAlo[o + 1] = l23;
        }
#pragma unroll
        for (int t = 0; t < 4; t++) {
            int idx = tid + t * 256;           // 0..1023
            int z = idx >> 9;                  // 512 per z
            int rem = idx & 511;
            int r = rem >> 4, c4 = (rem & 15) * 4;
            const float* Wz = z ? W1 : W0;
            float4 v = *(const float4*)&Wz[(size_t)(k0 + r) * Nc + c0 + c4];
            uint32_t h01, h23, l01, l23;
            cvt4(v, h01, h23, l01, l23);
            int o = r * STRB + (c4 >> 1);
            sBhi[z][o] = h01; sBhi[z][o + 1] = h23;
            sBlo[z][o] = l01; sBlo[z][o + 1] = l23;
        }
        __syncthreads();

#pragma unroll
        for (int s = 0; s < 2; s++) {
            uint32_t aH[2][4], aL[2][4];
#pragma unroll
            for (int ii = 0; ii < 2; ii++) {
                int tile = lane >> 3, rr = lane & 7;
                int row = wm * 32 + ii * 16 + (tile & 1) * 8 + rr;
                int kk = s * 16 + (tile >> 1) * 8;
                uint32_t off = (uint32_t)(row * STRA) * 4u + (uint32_t)kk * 2u;
                ldm_x4(aH[ii], aHiB + off);
                ldm_x4(aL[ii], aLoB + off);
            }
            int q = lane >> 3, rr = lane & 7;
            int krow = s * 16 + (q & 1) * 8 + rr;
#pragma unroll
            for (int z = 0; z < 2; z++) {
                uint32_t zb = (uint32_t)(z * 32 * STRB * 4);
                uint32_t bH4[2][4], bL4[2][4];
#pragma unroll
                for (int j2 = 0; j2 < 2; j2++) {
                    int ncol = wn * 32 + (j2 * 2 + (q >> 1)) * 8;
                    uint32_t off = (uint32_t)(krow * STRB) * 4u + (uint32_t)ncol * 2u;
                    ldm_x4t(bH4[j2], bHiB0 + zb + off);
                    ldm_x4t(bL4[j2], bLoB0 + zb + off);
                }
#pragma unroll
                for (int ii = 0; ii < 2; ii++)
#pragma unroll
                    for (int j = 0; j < 4; j++) {
                        uint32_t bh0 = bH4[j >> 1][(j & 1) * 2];
                        uint32_t bh1 = bH4[j >> 1][(j & 1) * 2 + 1];
                        uint32_t bl0 = bL4[j >> 1][(j & 1) * 2];
                        uint32_t bl1 = bL4[j >> 1][(j & 1) * 2 + 1];
                        mma_bf16(acc[z][ii][j], aH[ii], bh0, bh1);
                        mma_bf16(acc[z][ii][j], aH[ii], bl0, bl1);
                        mma_bf16(acc[z][ii][j], aL[ii], bh0, bh1);
                    }
            }
        }
        __syncthreads();
    }

    int g = lane >> 2, tg = lane & 3;
#pragma unroll
    for (int z = 0; z < 2; z++) {
        const float* bias = z ? bias1 : bias0;
        float* out        = z ? out1 : out0;
#pragma unroll
        for (int i = 0; i < 2; i++) {
            int r1 = row0 + wm * 32 + i * 16 + g;
            int r2 = r1 + 8;
#pragma unroll
            for (int j = 0; j < 4; j++) {
                int col = c0 + wn * 32 + j * 8 + tg * 2;
                float2 bv = *(const float2*)&bias[col];
                if (r1 < M) {
                    float2 o = make_float2(acc[z][i][j][0] + bv.x, acc[z][i][j][1] + bv.y);
                    *(float2*)&out[(size_t)r1 * Nc + col] = o;
                }
                if (r2 < M) {
                    float2 o = make_float2(acc[z][i][j][2] + bv.x, acc[z][i][j][3] + bv.y);
                    *(float2*)&out[(size_t)r2 * Nc + col] = o;
                }
            }
        }
    }
}

// ======================= tensorized edge-score kernel (CSR order) =========
template <int C>
__global__ void __launch_bounds__(256, 2)
k_score_mma(const float* __restrict__ eattr, const float* __restrict__ We,
            const float* __restrict__ att,
            const float* __restrict__ xl, const float* __restrict__ xr) {
    constexpr int STRC = C / 2 + 4;            // We smem row stride (u32)
    constexpr int ASZ = 128 * STRA * 4;        // 10240
    constexpr int BSZ = 32 * STRC * 4;
    constexpr int OFF_ALO = ASZ;
    constexpr int OFF_BHI = 2 * ASZ;
    constexpr int OFF_BLO = 2 * ASZ + BSZ;
    constexpr int OFF_SRC = 2 * ASZ + 2 * BSZ;
    constexpr int OFF_DST = OFF_SRC + 512;
    constexpr int OFF_ATT = OFF_DST + 512;
    constexpr int OFF_SC  = OFF_ATT + C * 4;

    extern __shared__ char smem[];
    uint32_t sb = smem_u32(smem);
    uint32_t* sAhi = (uint32_t*)smem;
    uint32_t* sAlo = (uint32_t*)(smem + OFF_ALO);
    uint32_t* sBhi = (uint32_t*)(smem + OFF_BHI);
    uint32_t* sBlo = (uint32_t*)(smem + OFF_BLO);
    int* ssrc   = (int*)(smem + OFF_SRC);
    int* sdst   = (int*)(smem + OFF_DST);
    float* satt = (float*)(smem + OFF_ATT);
    float* sscore = (float*)(smem + OFF_SC);

    int tid = threadIdx.x, lane = tid & 31, w = tid >> 5;
    int wm = w & 3, wn = w >> 2;
    int r0 = blockIdx.x * 128;

    // ---- A: eattr rows (via CSR eid) 128x32 -> hi/lo bf16
#pragma unroll
    for (int t = 0; t < 4; t++) {
        int idx = tid + t * 256;
        int r = idx >> 3, c4 = (idx & 7) * 4;
        float4 v = make_float4(0.f, 0.f, 0.f, 0.f);
        if (r0 + r < EE) {
            int e = g_eid[r0 + r];
            v = *(const float4*)&eattr[(size_t)e * ED + c4];
        }
        uint32_t h01, h23, l01, l23;
        cvt4(v, h01, h23, l01, l23);
        int o = r * STRA + (c4 >> 1);
        sAhi[o] = h01; sAhi[o + 1] = h23;
        sAlo[o] = l01; sAlo[o + 1] = l23;
    }
    // ---- B: We 32xC -> hi/lo bf16
    for (int idx = tid; idx < 32 * (C / 4); idx += 256) {
        int r = idx / (C / 4), c4 = (idx % (C / 4)) * 4;
        float4 v = *(const float4*)&We[(size_t)r * C + c4];
        uint32_t h01, h23, l01, l23;
        cvt4(v, h01, h23, l01, l23);
        int o = r * STRC + (c4 >> 1);
        sBhi[o] = h01; sBhi[o + 1] = h23;
        sBlo[o] = l01; sBlo[o + 1] = l23;
    }
    if (tid < 128) {
        int t = r0 + tid;
        ssrc[tid] = (t < EE) ? g_src_csr[t] : 0;
        sdst[tid] = (t < EE) ? g_dst_csr[t] : 0;
        sscore[tid] = 0.f;
    }
    for (int c = tid; c < C; c += 256) satt[c] = att[c];
    __syncthreads();

    // ---- A fragments (K=32 fixed, loaded once)
    uint32_t aH[2][2][4], aL[2][2][4];   // [s][ii]
#pragma unroll
    for (int s = 0; s < 2; s++)
#pragma unroll
        for (int ii = 0; ii < 2; ii++) {
            int tile = lane >> 3, rr = lane & 7;
            int row = wm * 32 + ii * 16 + (tile & 1) * 8 + rr;
            int kk = s * 16 + (tile >> 1) * 8;
            uint32_t off = (uint32_t)(row * STRA) * 4u + (uint32_t)kk * 2u;
            ldm_x4(aH[s][ii], sb + off);
            ldm_x4(aL[s][ii], sb + OFF_ALO + off);
        }

    int g = lane >> 2, tg = lane & 3;
    float sc[2][2] = {{0.f, 0.f}, {0.f, 0.f}};   // [ii][rowhalf]

#pragma unroll
    for (int nb = 0; nb < C / 64; nb++) {
        float acc[2][4][4];
#pragma unroll
        for (int ii = 0; ii < 2; ii++)
#pragma unroll
            for (int j = 0; j < 4; j++)
#pragma unroll
                for (int q = 0; q < 4; q++) acc[ii][j][q] = 0.f;

#pragma unroll
        for (int s = 0; s < 2; s++) {
            int q = lane >> 3, rr = lane & 7;
            int krow = s * 16 + (q & 1) * 8 + rr;
            uint32_t bH4[2][4], bL4[2][4];
#pragma unroll
            for (int j2 = 0; j2 < 2; j2++) {
                int ncol = nb * 64 + wn * 32 + (j2 * 2 + (q >> 1)) * 8;
                uint32_t off = (uint32_t)(krow * STRC) * 4u + (uint32_t)ncol * 2u;
                ldm_x4t(bH4[j2], sb + OFF_BHI + off);
                ldm_x4t(bL4[j2], sb + OFF_BLO + off);
            }
#pragma unroll
            for (int ii = 0; ii < 2; ii++)
#pragma unroll
                for (int j = 0; j < 4; j++) {
                    uint32_t bh0 = bH4[j >> 1][(j & 1) * 2];
                    uint32_t bh1 = bH4[j >> 1][(j & 1) * 2 + 1];
                    uint32_t bl0 = bL4[j >> 1][(j & 1) * 2];
                    uint32_t bl1 = bL4[j >> 1][(j & 1) * 2 + 1];
                    mma_bf16(acc[ii][j], aH[s][ii], bh0, bh1);
                    mma_bf16(acc[ii][j], aH[s][ii], bl0, bl1);
                    mma_bf16(acc[ii][j], aL[s][ii], bh0, bh1);
                }
        }

        // ---- epilogue: gather xl/xr (xr has dst-run locality), leaky, att
#pragma unroll
        for (int ii = 0; ii < 2; ii++) {
            int row1 = wm * 32 + ii * 16 + g;
            int row2 = row1 + 8;
            int s1 = ssrc[row1], d1 = sdst[row1];
            int s2 = ssrc[row2], d2 = sdst[row2];
#pragma unroll
            for (int j = 0; j < 4; j++) {
                int col = nb * 64 + wn * 32 + j * 8 + tg * 2;
                float2 av = *(float2*)&satt[col];
                float2 l1 = *(const float2*)&xl[(size_t)s1 * C + col];
                float2 q1 = *(const float2*)&xr[(size_t)d1 * C + col];
                float2 l2 = *(const float2*)&xl[(size_t)s2 * C + col];
                float2 q2 = *(const float2*)&xr[(size_t)d2 * C + col];
                float t0 = acc[ii][j][0] + l1.x + q1.x; t0 = t0 > 0.f ? t0 : 0.2f * t0;
                float t1 = acc[ii][j][1] + l1.y + q1.y; t1 = t1 > 0.f ? t1 : 0.2f * t1;
                float t2 = acc[ii][j][2] + l2.x + q2.x; t2 = t2 > 0.f ? t2 : 0.2f * t2;
                float t3 = acc[ii][j][3] + l2.y + q2.y; t3 = t3 > 0.f ? t3 : 0.2f * t3;
                sc[ii][0] += av.x * t0 + av.y * t1;
                sc[ii][1] += av.x * t2 + av.y * t3;
            }
        }
    }

    // ---- reduce across tg lanes, combine across wn warps via smem atomics
#pragma unroll
    for (int ii = 0; ii < 2; ii++)
#pragma unroll
        for (int h = 0; h < 2; h++) {
            float v = sc[ii][h];
            v += __shfl_xor_sync(0xffffffffu, v, 1);
            v += __shfl_xor_sync(0xffffffffu, v, 2);
            if (tg == 0) {
                int row = wm * 32 + ii * 16 + g + h * 8;
                atomicAdd(&sscore[row], v);
            }
        }
    __syncthreads();
    if (tid < 128 && r0 + tid < EE) g_escore[r0 + tid] = sscore[tid];
}

// ======================= self-loop score per node =========================
template <int C>
__global__ void k_eself(const float* __restrict__ We, const float* __restrict__ att,
                        const float* __restrict__ xl, const float* __restrict__ xr) {
    int gw = (blockIdx.x * blockDim.x + threadIdx.x) >> 5;
    int lane = threadIdx.x & 31;
    if (gw >= NN) return;
    float la = g_loopattr[(size_t)gw * ED + lane];
    float acc = 0.f;
#pragma unroll
    for (int jj = 0; jj < C / 32; jj++) {
        int j = jj * 32 + lane;
        float v = xl[(size_t)gw * C + j] + xr[(size_t)gw * C + j];
#pragma unroll
        for (int k = 0; k < ED; k++)
            v += __shfl_sync(0xffffffffu, la, k) * We[k * C + j];
        v = v > 0.f ? v : 0.2f * v;
        acc += att[j] * v;
    }
#pragma unroll
    for (int off = 16; off; off >>= 1) acc += __shfl_xor_sync(0xffffffffu, acc, off);
    if (lane == 0) g_eself[gw] = acc;
}

// ======================= softmax + aggregation (warp/node, CSR) ===========
template <int C>
__global__ void k_aggregate(const float* __restrict__ bias,
                            const float* __restrict__ xl,
                            float* __restrict__ outp) {
    int gw = (blockIdx.x * blockDim.x + threadIdx.x) >> 5;
    int lane = threadIdx.x & 31;
    if (gw >= NN) return;
    int beg = g_ptr[gw], end = g_ptr[gw + 1];

    float m = g_eself[gw];
    for (int t = beg + lane; t < end; t += 32) m = fmaxf(m, g_escore[t]);
#pragma unroll
    for (int off = 16; off; off >>= 1) m = fmaxf(m, __shfl_xor_sync(0xffffffffu, m, off));

    float4 acc[C / 128];
#pragma unroll
    for (int jj = 0; jj < C / 128; jj++) acc[jj] = make_float4(0.f, 0.f, 0.f, 0.f);
    float denom = 0.f;

    // unrolled-by-2 edge loop for MLP
    int t = beg;
    for (; t + 1 < end; t += 2) {
        float w0 = expf(g_escore[t] - m);
        float w1 = expf(g_escore[t + 1] - m);
        int s0 = g_src_csr[t], s1 = g_src_csr[t + 1];
        denom += w0 + w1;
#pragma unroll
        for (int jj = 0; jj < C / 128; jj++) {
            float4 x0 = *(const float4*)&xl[(size_t)s0 * C + jj * 128 + lane * 4];
            float4 x1 = *(const float4*)&xl[(size_t)s1 * C + jj * 128 + lane * 4];
            acc[jj].x += w0 * x0.x + w1 * x1.x;
            acc[jj].y += w0 * x0.y + w1 * x1.y;
            acc[jj].z += w0 * x0.z + w1 * x1.z;
            acc[jj].w += w0 * x0.w + w1 * x1.w;
        }
    }
    if (t < end) {
        float w0 = expf(g_escore[t] - m);
        int s0 = g_src_csr[t];
        denom += w0;
#pragma unroll
        for (int jj = 0; jj < C / 128; jj++) {
            float4 x0 = *(const float4*)&xl[(size_t)s0 * C + jj * 128 + lane * 4];
            acc[jj].x += w0 * x0.x; acc[jj].y += w0 * x0.y;
            acc[jj].z += w0 * x0.z; acc[jj].w += w0 * x0.w;
        }
    }
    float ws = expf(g_eself[gw] - m);
    denom += ws;
#pragma unroll
    for (int jj = 0; jj < C / 128; jj++) {
        float4 x4 = *(const float4*)&xl[(size_t)gw * C + jj * 128 + lane * 4];
        acc[jj].x += ws * x4.x; acc[jj].y += ws * x4.y;
        acc[jj].z += ws * x4.z; acc[jj].w += ws * x4.w;
    }

    float inv = 1.f / denom;
#pragma unroll
    for (int jj = 0; jj < C / 128; jj++) {
        int c = jj * 128 + lane * 4;
        float4 b4 = *(const float4*)&bias[c];
        float4 o;
        o.x = fmaxf(acc[jj].x * inv + b4.x, 0.f);
        o.y = fmaxf(acc[jj].y * inv + b4.y, 0.f);
        o.z = fmaxf(acc[jj].z * inv + b4.z, 0.f);
        o.w = fmaxf(acc[jj].w * inv + b4.w, 0.f);
        *(float4*)&outp[(size_t)gw * C + c] = o;
    }
}

// ======================= global mean pool =================================
#define NPB 196
__global__ void k_pool2(const int* __restrict__ batch) {
    int tid = threadIdx.x;                 // 128 threads = H2 columns
    int n0 = blockIdx.x * NPB;
    int n1 = min(n0 + NPB, NN);
    if (n0 >= n1) return;
    int curg = batch[n0];
    float acc = 0.f;
    for (int n = n0; n < n1; n++) {
        int g = batch[n];
        if (g != curg) {
            atomicAdd(&g_pool[curg * H2 + tid], acc);
            acc = 0.f;
            curg = g;
        }
        acc += g_h2[(size_t)n * H2 + tid];
    }
    atomicAdd(&g_pool[curg * H2 + tid], acc);
}

// ======================= MLP head =========================================
__device__ __forceinline__ int lowerb(const int* b, int val) {
    int lo = 0, hi = NN;
    while (lo < hi) { int m = (lo + hi) >> 1; if (b[m] < val) lo = m + 1; else hi = m; }
    return lo;
}

__global__ void k_head(const int* __restrict__ batch,
                       const float* __restrict__ Wd1, const float* __restrict__ bd1,
                       const float* __restrict__ gma, const float* __restrict__ bta,
                       const float* __restrict__ mean, const float* __restrict__ var,
                       const float* __restrict__ Wd2, const float* __restrict__ bd2,
                       float* __restrict__ out) {
    __shared__ float sp[GG * H2];
    __shared__ float sh[GG * HD];
    __shared__ float scnt[GG];
    int tid = threadIdx.x;
    if (tid < GG)
        scnt[tid] = (float)(lowerb(batch, tid + 1) - lowerb(batch, tid));
    __syncthreads();
    for (int idx = tid; idx < GG * H2; idx += blockDim.x) {
        int g = idx / H2;
        sp[idx] = g_pool[idx] / fmaxf(scnt[g], 1.f);
    }
    __syncthreads();
    for (int idx = tid; idx < GG * HD; idx += blockDim.x) {
        int g = idx / HD, h = idx - g * HD;
        float a = bd1[h];
        for (int k = 0; k < H2; k++) a += sp[g * H2 + k] * Wd1[k * HD + h];
        a = (a - mean[h]) / sqrtf(var[h] + 1e-5f) * gma[h] + bta[h];
        a = a > 0.f ? a : 0.1f * a;
        sh[idx] = a;
    }
    __syncthreads();
    for (int idx = tid; idx < GG * OUTD; idx += blockDim.x) {
        int g = idx / OUTD, o = idx - g * OUTD;
        float a = bd2[o];
        for (int k = 0; k < HD; k++) a += sh[g * HD + k] * Wd2[k * OUTD + o];
        out[idx] = a;
    }
}

// ======================= launcher =========================================
extern "C" void kernel_launch(void* const* d_in, const int* in_sizes, int n_in,
                              void* d_out, int out_size) {
    const float* node_attr = (const float*)d_in[0];
    const float* edge_attr = (const float*)d_in[1];
    const int*   esrc      = (const int*)d_in[2];
    const int*   edst      = (const int*)d_in[3];
    const int*   batch     = (const int*)d_in[4];
    const float *Wl1 = (const float*)d_in[5],  *bl1 = (const float*)d_in[6];
    const float *Wr1 = (const float*)d_in[7],  *br1 = (const float*)d_in[8];
    const float *We1 = (const float*)d_in[9],  *att1 = (const float*)d_in[10], *b1 = (const float*)d_in[11];
    const float *Wl2 = (const float*)d_in[12], *bl2 = (const float*)d_in[13];
    const float *Wr2 = (const float*)d_in[14], *br2 = (const float*)d_in[15];
    const float *We2 = (const float*)d_in[16], *att2 = (const float*)d_in[17], *b2 = (const float*)d_in[18];
    const float *Wd1 = (const float*)d_in[19], *bd1 = (const float*)d_in[20];
    const float *gma = (const float*)d_in[21], *bta = (const float*)d_in[22];
    const float *mean = (const float*)d_in[23], *var = (const float*)d_in[24];
    const float *Wd2 = (const float*)d_in[25], *bd2 = (const float*)d_in[26];
    float* out = (float*)d_out;

    float *p_xl, *p_xr, *p_h1, *p_h2, *p_pool;
    int *p_deg, *p_cur;
    cudaGetSymbolAddress((void**)&p_xl, g_xl);
    cudaGetSymbolAddress((void**)&p_xr, g_xr);
    cudaGetSymbolAddress((void**)&p_h1, g_h1);
    cudaGetSymbolAddress((void**)&p_h2, g_h2);
    cudaGetSymbolAddress((void**)&p_pool, g_pool);
    cudaGetSymbolAddress((void**)&p_deg, g_deg);
    cudaGetSymbolAddress((void**)&p_cur, g_cur);

    // dynamic smem sizes for score kernels
    const int SC1 = 2 * 10240 + 2 * (32 * (H1 / 2 + 4) * 4) + 512 + 512 + H1 * 4 + 512;
    const int SC2 = 2 * 10240 + 2 * (32 * (H2 / 2 + 4) * 4) + 512 + 512 + H2 * 4 + 512;
    cudaFuncSetAttribute(k_score_mma<H1>, cudaFuncAttributeMaxDynamicSharedMemorySize, SC1);
    cudaFuncSetAttribute(k_score_mma<H2>, cudaFuncAttributeMaxDynamicSharedMemorySize, SC2);

    // fork-join resources (created once; creation is not a captured op)
    cudaStream_t sB;
    cudaEvent_t evIn, evCsr, evGemm1, evSelf1, evGemm2, evSelf2;
    cudaStreamCreateWithFlags(&sB, cudaStreamNonBlocking);
    cudaEventCreateWithFlags(&evIn, cudaEventDisableTiming);
    cudaEventCreateWithFlags(&evCsr, cudaEventDisableTiming);
    cudaEventCreateWithFlags(&evGemm1, cudaEventDisableTiming);
    cudaEventCreateWithFlags(&evSelf1, cudaEventDisableTiming);
    cudaEventCreateWithFlags(&evGemm2, cudaEventDisableTiming);
    cudaEventCreateWithFlags(&evSelf2, cudaEventDisableTiming);

    cudaMemsetAsync(p_deg, 0, NN * sizeof(int), 0);
    cudaMemsetAsync(p_cur, 0, NN * sizeof(int), 0);
    cudaMemsetAsync(p_pool, 0, GG * H2 * sizeof(float), 0);

    int nodeWB = (NN * 32 + 255) / 256;   // warp-per-node blocks
    int rowT = (NN + 127) / 128;          // 391
    int edgeT = (EE + 127) / 128;         // 3907

    // ---- fork: branch B = CSR construction; branch A (stream 0) = GEMM
    cudaEventRecord(evIn, 0);
    cudaStreamWaitEvent(sB, evIn, 0);
    k_hist<<<(EE + 255) / 256, 256, 0, sB>>>(edst);
    k_scan_partial<<<NCHUNK, 1024, 0, sB>>>();
    k_scan_bsum<<<1, 64, 0, sB>>>();
    k_scan_final<<<NCHUNK, 1024, 0, sB>>>();
    k_scatter<<<(EE + 255) / 256, 256, 0, sB>>>(esrc, edst);
    k_loopmean<<<nodeWB, 256, 0, sB>>>(edge_attr);
    cudaEventRecord(evCsr, sB);

    k_mma_nodeZ<DIN><<<dim3(rowT, H1 / 64), 256, 0, 0>>>(
        node_attr, Wl1, bl1, p_xl, Wr1, br1, p_xr, NN, H1);
    cudaEventRecord(evGemm1, 0);

    // ---- layer 1: score on stream 0 (needs CSR + xl/xr); eself on sB
    cudaStreamWaitEvent(0, evCsr, 0);
    k_score_mma<H1><<<edgeT, 256, SC1, 0>>>(edge_attr, We1, att1, p_xl, p_xr);
    cudaStreamWaitEvent(sB, evGemm1, 0);
    k_eself<H1><<<nodeWB, 256, 0, sB>>>(We1, att1, p_xl, p_xr);
    cudaEventRecord(evSelf1, sB);
    cudaStreamWaitEvent(0, evSelf1, 0);
    k_aggregate<H1><<<nodeWB, 256, 0, 0>>>(b1, p_xl, p_h1);

    // ---- layer 2
    k_mma_nodeZ<H1><<<dim3(rowT, H2 / 64), 256, 0, 0>>>(
        p_h1, Wl2, bl2, p_xl, Wr2, br2, p_xr, NN, H2);
    cudaEventRecord(evGemm2, 0);
    k_score_mma<H2><<<edgeT, 256, SC2, 0>>>(edge_attr, We2, att2, p_xl, p_xr);
    cudaStreamWaitEvent(sB, evGemm2, 0);
    k_eself<H2><<<nodeWB, 256, 0, sB>>>(We2, att2, p_xl, p_xr);
    cudaEventRecord(evSelf2, sB);
    cudaStreamWaitEvent(0, evSelf2, 0);
    k_aggregate<H2><<<nodeWB, 256, 0, 0>>>(b2, p_xl, p_h2);

    // ---- pool + head
    k_pool2<<<(NN + NPB - 1) / NPB, 128, 0, 0>>>(batch);
    k_head<<<1, 512, 0, 0>>>(batch, Wd1, bd1, gma, bta, mean, var, Wd2, bd2, out);
}